// round 2
// baseline (speedup 1.0000x reference)
#include <cuda_runtime.h>
#include <cuda_bf16.h>

#define BB    64
#define NN    25200
#define TOPK  1024
#define CAP   4096
#define NBINS 1024
#define CONF  0.25f
#define IOUT  0.45f

// ---------------- scratch (device globals: allocation-free) ----------------
__device__ float              g_scores[BB * NN];
__device__ unsigned int       g_hist[BB * NBINS];
__device__ int                g_thresh[BB];
__device__ int                g_count[BB];
__device__ unsigned long long g_cand[BB * CAP];
__device__ int                g_topidx[BB * TOPK];
__device__ float              g_topscore[BB * TOPK];
__device__ float4             g_boxes[BB * TOPK];
__device__ unsigned int       g_mask[BB * TOPK * 32];

// ---------------- K0: zero hist + counters ----------------
__global__ void k_zero() {
    int b = blockIdx.x, t = threadIdx.x;
    g_hist[b * NBINS + t] = 0u;
    if (t == 0) g_count[b] = 0;
}

// ---------------- K1: score + histogram ----------------
__global__ __launch_bounds__(256) void k_score(const float* __restrict__ x) {
    int b = blockIdx.y;
#pragma unroll
    for (int a = 0; a < 4; ++a) {
        int n = blockIdx.x * 1024 + a * 256 + threadIdx.x;
        if (n < NN) {
            const float4* row = (const float4*)(x + (long)(b * NN + n) * 16);
            float obj = row[1].x;   // col 4
            float cls = row[3].w;   // col 15
            float s = obj * cls;
            g_scores[b * NN + n] = s;
            if (s > CONF) {
                int bin = (int)((s - CONF) * (1024.0f / 0.75f));
                bin = min(bin, NBINS - 1);
                atomicAdd(&g_hist[b * NBINS + bin], 1u);
            }
        }
    }
}

// ---------------- K2: per-image threshold bin via suffix scan ----------------
__global__ __launch_bounds__(1024) void k_thresh() {
    __shared__ unsigned int sh[NBINS];
    __shared__ int best;
    int b = blockIdx.x, t = threadIdx.x;
    sh[t] = g_hist[b * NBINS + t];
    if (t == 0) best = 0;
    __syncthreads();
    for (int off = 1; off < NBINS; off <<= 1) {
        unsigned int v = (t + off < NBINS) ? sh[t + off] : 0u;
        __syncthreads();
        sh[t] += v;
        __syncthreads();
    }
    if (sh[t] >= TOPK) atomicMax(&best, t);
    __syncthreads();
    if (t == 0) g_thresh[b] = best;
}

// ---------------- K3: compact candidates above threshold bin ----------------
__global__ __launch_bounds__(256) void k_compact() {
    int b = blockIdx.y;
    int T = g_thresh[b];
#pragma unroll
    for (int a = 0; a < 4; ++a) {
        int n = blockIdx.x * 1024 + a * 256 + threadIdx.x;
        if (n < NN) {
            float s = g_scores[b * NN + n];
            if (s > CONF) {
                int bin = min((int)((s - CONF) * (1024.0f / 0.75f)), NBINS - 1);
                if (bin >= T) {
                    int pos = atomicAdd(&g_count[b], 1);
                    if (pos < CAP) {
                        unsigned long long key =
                            ((unsigned long long)__float_as_uint(s) << 32) |
                            (unsigned long long)(0xFFFFFFFFu - (unsigned)n);
                        g_cand[b * CAP + pos] = key;
                    }
                }
            }
        }
    }
}

// ---------------- K4: bitonic sort (desc) + gather boxes ----------------
__global__ __launch_bounds__(1024) void k_sort(const float* __restrict__ x) {
    __shared__ unsigned long long sk[CAP];
    int b = blockIdx.x, t = threadIdx.x;
    int cnt = min(g_count[b], CAP);
    for (int e = t; e < CAP; e += 1024)
        sk[e] = (e < cnt) ? g_cand[b * CAP + e] : 0ULL;
    __syncthreads();
    for (int k = 2; k <= CAP; k <<= 1) {
        for (int j = k >> 1; j > 0; j >>= 1) {
            for (int e = t; e < CAP; e += 1024) {
                int ixj = e ^ j;
                if (ixj > e) {
                    unsigned long long a = sk[e], c = sk[ixj];
                    bool desc = ((e & k) == 0);
                    if (desc ? (a < c) : (a > c)) { sk[e] = c; sk[ixj] = a; }
                }
            }
            __syncthreads();
        }
    }
    if (t < TOPK) {
        unsigned long long key = sk[t];
        float s = __uint_as_float((unsigned)(key >> 32));
        int idx = (key == 0ULL) ? 0 : (int)(0xFFFFFFFFu - (unsigned)(key & 0xFFFFFFFFu));
        if (idx < 0 || idx >= NN) idx = 0;
        g_topscore[b * TOPK + t] = (key == 0ULL) ? 0.0f : s;
        g_topidx[b * TOPK + t] = idx;
        const float4* row = (const float4*)(x + (long)(b * NN + idx) * 16);
        float4 c0 = row[0];
        float hw = c0.z * 0.5f, hh = c0.w * 0.5f;
        g_boxes[b * TOPK + t] = make_float4(c0.x - hw, c0.y - hh, c0.x + hw, c0.y + hh);
    }
}

// ---------------- K5: suppression bitmask (upper triangle) ----------------
__global__ __launch_bounds__(128) void k_mask() {
    __shared__ float4 sb[TOPK];
    __shared__ float  sa[TOPK];
    int b = blockIdx.y, t = threadIdx.x;
    for (int e = t; e < TOPK; e += 128) {
        float4 v = g_boxes[b * TOPK + e];
        sb[e] = v;
        sa[e] = fmaxf(v.z - v.x, 0.0f) * fmaxf(v.w - v.y, 0.0f);
    }
    __syncthreads();
    int i = blockIdx.x * 128 + t;
    float4 bi = sb[i];
    float ai = sa[i];
    unsigned int* out = &g_mask[(long)(b * TOPK + i) * 32];
    int w0 = i >> 5;
    for (int w = 0; w < w0; ++w) out[w] = 0u;
    for (int w = w0; w < 32; ++w) {
        unsigned int word = 0u;
        int j0 = w * 32;
#pragma unroll 8
        for (int jj = 0; jj < 32; ++jj) {
            int j = j0 + jj;
            float4 bj = sb[j];
            float ix1 = fmaxf(bi.x, bj.x), iy1 = fmaxf(bi.y, bj.y);
            float ix2 = fminf(bi.z, bj.z), iy2 = fminf(bi.w, bj.w);
            float inter = fmaxf(ix2 - ix1, 0.0f) * fmaxf(iy2 - iy1, 0.0f);
            float den = (ai + sa[j] - inter) + 1e-9f;
            float diff = inter - IOUT * den;
            bool bit;
            if (fabsf(diff) > 1e-5f * den) bit = (diff > 0.0f);
            else bit = (__fdiv_rn(inter, den) > IOUT);  // IEEE-exact borderline
            bit = bit && (j > i);
            word |= ((unsigned)bit) << jj;
        }
        out[w] = word;
    }
}

// ---------------- K6: sequential greedy scan (1 warp/image) + output ----------------
__global__ __launch_bounds__(1024) void k_scan_out(const float* __restrict__ x,
                                                   float* __restrict__ out) {
    __shared__ unsigned int validw[32];
    __shared__ unsigned int keepw[32];
    int b = blockIdx.x, t = threadIdx.x;
    float sc = g_topscore[b * TOPK + t];
    unsigned int vb = __ballot_sync(0xffffffffu, sc > 0.0f);
    if ((t & 31) == 0) validw[t >> 5] = vb;
    __syncthreads();

    if (t < 32) {
        int lane = t;
        unsigned int vw = validw[lane];
        const unsigned int* mrow = &g_mask[(long)(b * TOPK) * 32];
        unsigned int removed = 0u, kw = 0u;
        unsigned int buf[8];
#pragma unroll
        for (int p = 0; p < 8; ++p) buf[p] = mrow[p * 32 + lane];
#pragma unroll 8
        for (int i = 0; i < 1024; ++i) {
            unsigned int cur = buf[i & 7];
            int pre = i + 8;
            buf[i & 7] = (pre < 1024) ? mrow[pre * 32 + lane] : 0u;  // 8-deep prefetch
            unsigned int ok = vw & ~removed;
            int w = i >> 5;
            unsigned int okw = __shfl_sync(0xffffffffu, ok, w);
            unsigned int kept = (okw >> (i & 31)) & 1u;
            removed |= kept ? cur : 0u;
            if (lane == w) kw |= kept << (i & 31);
        }
        keepw[lane] = kw;
    }
    __syncthreads();

    unsigned int kept = (keepw[t >> 5] >> (t & 31)) & 1u;
    float4* orow = (float4*)(out + (long)(b * TOPK + t) * 16);
    if (kept) {
        int idx = g_topidx[b * TOPK + t];
        const float4* row = (const float4*)(x + (long)(b * NN + idx) * 16);
        float4 c0 = row[0], c1 = row[1], c2 = row[2], c3 = row[3];
        float hw = c0.z * 0.5f, hh = c0.w * 0.5f;
        orow[0] = make_float4(c0.x - hw, c0.y - hh, c0.x + hw, c0.y + hh);
        orow[1] = make_float4(sc, c1.y, c1.z, c1.w);   // conf, lm cols 5..7
        orow[2] = c2;                                   // lm cols 8..11
        orow[3] = make_float4(c3.x, c3.y, c3.z, 0.0f);  // lm 12..14, cls_id=0
    } else {
        float4 z = make_float4(0.0f, 0.0f, 0.0f, 0.0f);
        orow[0] = z; orow[1] = z; orow[2] = z; orow[3] = z;
    }
}

// ---------------- launch ----------------
extern "C" void kernel_launch(void* const* d_in, const int* in_sizes, int n_in,
                              void* d_out, int out_size) {
    const float* x = (const float*)d_in[0];
    float* out = (float*)d_out;
    (void)in_sizes; (void)n_in; (void)out_size;

    k_zero<<<BB, 1024>>>();
    {
        dim3 g((NN + 1023) / 1024, BB);
        k_score<<<g, 256>>>(x);
    }
    k_thresh<<<BB, 1024>>>();
    {
        dim3 g((NN + 1023) / 1024, BB);
        k_compact<<<g, 256>>>();
    }
    k_sort<<<BB, 1024>>>(x);
    {
        dim3 g(8, BB);
        k_mask<<<g, 128>>>();
    }
    k_scan_out<<<BB, 1024>>>(x, out);
}

// round 3
// speedup vs baseline: 1.1267x; 1.1267x over previous
#include <cuda_runtime.h>
#include <cuda_bf16.h>

#define BB    64
#define NN    25200
#define TOPK  1024
#define CAP   4096
#define NBINS 1024
#define CONF  0.25f
#define IOUT  0.45f

// ---------------- scratch (device globals: allocation-free) ----------------
__device__ float              g_scores[BB * NN];
__device__ unsigned int       g_hist[BB * NBINS];
__device__ int                g_thresh[BB];
__device__ int                g_count[BB];
__device__ unsigned long long g_cand[BB * CAP];
__device__ int                g_topidx[BB * TOPK];
__device__ float              g_topscore[BB * TOPK];
__device__ float4             g_boxes[BB * TOPK];
__device__ unsigned int       g_mask[BB * TOPK * 32];

// ---------------- K0: zero hist + counters ----------------
__global__ void k_zero() {
    int b = blockIdx.x, t = threadIdx.x;
    g_hist[b * NBINS + t] = 0u;
    if (t == 0) g_count[b] = 0;
}

// ---------------- K1: score + histogram ----------------
__global__ __launch_bounds__(256) void k_score(const float* __restrict__ x) {
    int b = blockIdx.y;
#pragma unroll
    for (int a = 0; a < 4; ++a) {
        int n = blockIdx.x * 1024 + a * 256 + threadIdx.x;
        if (n < NN) {
            const float4* row = (const float4*)(x + (long)(b * NN + n) * 16);
            float obj = row[1].x;   // col 4
            float cls = row[3].w;   // col 15
            float s = obj * cls;
            g_scores[b * NN + n] = s;
            if (s > CONF) {
                int bin = (int)((s - CONF) * (1024.0f / 0.75f));
                bin = min(bin, NBINS - 1);
                atomicAdd(&g_hist[b * NBINS + bin], 1u);
            }
        }
    }
}

// ---------------- K2: per-image threshold bin via suffix scan ----------------
__global__ __launch_bounds__(1024) void k_thresh() {
    __shared__ unsigned int sh[NBINS];
    __shared__ int best;
    int b = blockIdx.x, t = threadIdx.x;
    sh[t] = g_hist[b * NBINS + t];
    if (t == 0) best = 0;
    __syncthreads();
    for (int off = 1; off < NBINS; off <<= 1) {
        unsigned int v = (t + off < NBINS) ? sh[t + off] : 0u;
        __syncthreads();
        sh[t] += v;
        __syncthreads();
    }
    if (sh[t] >= TOPK) atomicMax(&best, t);
    __syncthreads();
    if (t == 0) g_thresh[b] = best;
}

// ---------------- K3: compact candidates (warp-aggregated atomics) ----------------
__global__ __launch_bounds__(256) void k_compact() {
    int b = blockIdx.y;
    int T = g_thresh[b];
    int lane = threadIdx.x & 31;
#pragma unroll
    for (int a = 0; a < 4; ++a) {
        int n = blockIdx.x * 1024 + a * 256 + threadIdx.x;
        bool sel = false;
        float s = 0.0f;
        if (n < NN) {
            s = g_scores[b * NN + n];
            if (s > CONF) {
                int bin = min((int)((s - CONF) * (1024.0f / 0.75f)), NBINS - 1);
                sel = (bin >= T);
            }
        }
        unsigned int m = __ballot_sync(0xffffffffu, sel);
        if (m) {
            int base = 0;
            if (lane == 0) base = atomicAdd(&g_count[b], __popc(m));
            base = __shfl_sync(0xffffffffu, base, 0);
            if (sel) {
                int pos = base + __popc(m & ((1u << lane) - 1u));
                if (pos < CAP) {
                    unsigned long long key =
                        ((unsigned long long)__float_as_uint(s) << 32) |
                        (unsigned long long)(0xFFFFFFFFu - (unsigned)n);
                    g_cand[b * CAP + pos] = key;
                }
            }
        }
    }
}

// ---------------- K4: bitonic sort (desc) + gather boxes ----------------
__global__ __launch_bounds__(1024) void k_sort(const float* __restrict__ x) {
    __shared__ unsigned long long sk[CAP];
    int b = blockIdx.x, t = threadIdx.x;
    int cnt = min(g_count[b], CAP);
    for (int e = t; e < CAP; e += 1024)
        sk[e] = (e < cnt) ? g_cand[b * CAP + e] : 0ULL;
    __syncthreads();
    for (int k = 2; k <= CAP; k <<= 1) {
        for (int j = k >> 1; j > 0; j >>= 1) {
            for (int e = t; e < CAP; e += 1024) {
                int ixj = e ^ j;
                if (ixj > e) {
                    unsigned long long a = sk[e], c = sk[ixj];
                    bool desc = ((e & k) == 0);
                    if (desc ? (a < c) : (a > c)) { sk[e] = c; sk[ixj] = a; }
                }
            }
            __syncthreads();
        }
    }
    if (t < TOPK) {
        unsigned long long key = sk[t];
        float s = __uint_as_float((unsigned)(key >> 32));
        int idx = (key == 0ULL) ? 0 : (int)(0xFFFFFFFFu - (unsigned)(key & 0xFFFFFFFFu));
        if (idx < 0 || idx >= NN) idx = 0;
        g_topscore[b * TOPK + t] = (key == 0ULL) ? 0.0f : s;
        g_topidx[b * TOPK + t] = idx;
        const float4* row = (const float4*)(x + (long)(b * NN + idx) * 16);
        float4 c0 = row[0];
        float hw = c0.z * 0.5f, hh = c0.w * 0.5f;
        g_boxes[b * TOPK + t] = make_float4(c0.x - hw, c0.y - hh, c0.x + hw, c0.y + hh);
    }
}

// ---------------- K5: suppression bitmask (branchless + deferred exact fixup) ----------------
// iou > 0.45  <=>  inter/((ai+aj-inter)+1e-9) > 0.45
//            <=>  1.45*inter - 0.45*(ai+aj) > 4.5e-10   (exactly, in reals)
// Cheap test uses pre-scaled areas (sv = 0.45*area); anything within the
// +-2e-5*s margin band (covers all f32 rounding drift + the 4.5e-10 shift,
// scale >= 5e-4 since areas >= 64) is resolved with the bit-exact reference
// expression using IEEE __fdiv_rn, once per 32-pair word (uniform-rare branch).
__global__ __launch_bounds__(128) void k_mask() {
    __shared__ float4 sb[TOPK];
    __shared__ float  sv[TOPK];   // 0.45 * area
    int b = blockIdx.y, t = threadIdx.x;
    for (int e = t; e < TOPK; e += 128) {
        float4 v = g_boxes[b * TOPK + e];
        sb[e] = v;
        sv[e] = 0.45f * (fmaxf(v.z - v.x, 0.0f) * fmaxf(v.w - v.y, 0.0f));
    }
    __syncthreads();
    int i = blockIdx.x * 128 + t;
    float4 bi = sb[i];
    float u = sv[i];
    unsigned int* out = &g_mask[(long)(b * TOPK + i) * 32];
    int w0 = i >> 5;
    for (int w = 0; w < w0; ++w) out[w] = 0u;
    int r = i & 31;
    unsigned int diagmask = 0xFFFFFFFEu << r;   // keep bits jj > r (r=31 -> 0)
    for (int w = w0; w < 32; ++w) {
        unsigned int word = 0u, nearm = 0u;
        int j0 = w * 32;
#pragma unroll
        for (int jj = 0; jj < 32; ++jj) {
            int j = j0 + jj;
            float4 bj = sb[j];
            float ix1 = fmaxf(bi.x, bj.x), iy1 = fmaxf(bi.y, bj.y);
            float ix2 = fminf(bi.z, bj.z), iy2 = fminf(bi.w, bj.w);
            float inter = fmaxf(ix2 - ix1, 0.0f) * fmaxf(iy2 - iy1, 0.0f);
            float s = u + sv[j];
            float diff2 = fmaf(1.45f, inter, -s);
            word  |= (diff2 > 0.0f)           ? (1u << jj) : 0u;
            nearm |= (fabsf(diff2) <= 2e-5f * s) ? (1u << jj) : 0u;
        }
        if (nearm) {   // extremely rare: exact IEEE path per borderline pair
            do {
                int jj = __ffs(nearm) - 1;
                nearm &= nearm - 1u;
                int j = j0 + jj;
                float4 bj = sb[j];
                float ai = fmaxf(bi.z - bi.x, 0.0f) * fmaxf(bi.w - bi.y, 0.0f);
                float aj = fmaxf(bj.z - bj.x, 0.0f) * fmaxf(bj.w - bj.y, 0.0f);
                float ix1 = fmaxf(bi.x, bj.x), iy1 = fmaxf(bi.y, bj.y);
                float ix2 = fminf(bi.z, bj.z), iy2 = fminf(bi.w, bj.w);
                float inter = fmaxf(ix2 - ix1, 0.0f) * fmaxf(iy2 - iy1, 0.0f);
                float den = (ai + aj - inter) + 1e-9f;
                bool bit = (__fdiv_rn(inter, den) > IOUT);
                word = bit ? (word | (1u << jj)) : (word & ~(1u << jj));
            } while (nearm);
        }
        if (w == w0) word &= diagmask;
        out[w] = word;
    }
}

// ---------------- K6: sequential greedy scan (1 warp/image) + output ----------------
__global__ __launch_bounds__(1024) void k_scan_out(const float* __restrict__ x,
                                                   float* __restrict__ out) {
    __shared__ unsigned int validw[32];
    __shared__ unsigned int keepw[32];
    int b = blockIdx.x, t = threadIdx.x;
    float sc = g_topscore[b * TOPK + t];
    unsigned int vb = __ballot_sync(0xffffffffu, sc > 0.0f);
    if ((t & 31) == 0) validw[t >> 5] = vb;
    __syncthreads();

    if (t < 32) {
        int lane = t;
        unsigned int vw = validw[lane];
        const unsigned int* mrow = &g_mask[(long)(b * TOPK) * 32];
        unsigned int removed = 0u, kw = 0u;
        unsigned int buf[8];
#pragma unroll
        for (int p = 0; p < 8; ++p) buf[p] = mrow[p * 32 + lane];
#pragma unroll 8
        for (int i = 0; i < 1024; ++i) {
            unsigned int cur = buf[i & 7];
            int pre = i + 8;
            buf[i & 7] = (pre < 1024) ? mrow[pre * 32 + lane] : 0u;  // 8-deep prefetch
            unsigned int ok = vw & ~removed;
            int w = i >> 5;
            unsigned int okw = __shfl_sync(0xffffffffu, ok, w);
            unsigned int kept = (okw >> (i & 31)) & 1u;
            removed |= kept ? cur : 0u;
            if (lane == w) kw |= kept << (i & 31);
        }
        keepw[lane] = kw;
    }
    __syncthreads();

    unsigned int kept = (keepw[t >> 5] >> (t & 31)) & 1u;
    float4* orow = (float4*)(out + (long)(b * TOPK + t) * 16);
    if (kept) {
        int idx = g_topidx[b * TOPK + t];
        const float4* row = (const float4*)(x + (long)(b * NN + idx) * 16);
        float4 c0 = row[0], c1 = row[1], c2 = row[2], c3 = row[3];
        float hw = c0.z * 0.5f, hh = c0.w * 0.5f;
        orow[0] = make_float4(c0.x - hw, c0.y - hh, c0.x + hw, c0.y + hh);
        orow[1] = make_float4(sc, c1.y, c1.z, c1.w);
        orow[2] = c2;
        orow[3] = make_float4(c3.x, c3.y, c3.z, 0.0f);
    } else {
        float4 z = make_float4(0.0f, 0.0f, 0.0f, 0.0f);
        orow[0] = z; orow[1] = z; orow[2] = z; orow[3] = z;
    }
}

// ---------------- launch ----------------
extern "C" void kernel_launch(void* const* d_in, const int* in_sizes, int n_in,
                              void* d_out, int out_size) {
    const float* x = (const float*)d_in[0];
    float* out = (float*)d_out;
    (void)in_sizes; (void)n_in; (void)out_size;

    k_zero<<<BB, 1024>>>();
    {
        dim3 g((NN + 1023) / 1024, BB);
        k_score<<<g, 256>>>(x);
    }
    k_thresh<<<BB, 1024>>>();
    {
        dim3 g((NN + 1023) / 1024, BB);
        k_compact<<<g, 256>>>();
    }
    k_sort<<<BB, 1024>>>(x);
    {
        dim3 g(8, BB);
        k_mask<<<g, 128>>>();
    }
    k_scan_out<<<BB, 1024>>>(x, out);
}

// round 4
// speedup vs baseline: 1.1974x; 1.0627x over previous
#include <cuda_runtime.h>
#include <cuda_bf16.h>

#define BB    64
#define NN    25200
#define TOPK  1024
#define CAP   4096
#define NBINS 1024
#define CONF  0.25f
#define IOUT  0.45f
#define CHUNK 788          // ceil(25200/32)
#define SEG   128          // per-warp candidate segment (CAP/32)

// ---------------- scratch (device globals: allocation-free) ----------------
__device__ float        g_scores[BB * NN];
__device__ unsigned int g_hist[BB * NBINS];
__device__ int          g_topidx[BB * TOPK];
__device__ float        g_topscore[BB * TOPK];
__device__ float4       g_boxes[BB * TOPK];     // rank-ordered boxes
__device__ float4       g_sbox[BB * TOPK];      // cell-ordered boxes
__device__ uint2        g_saux[BB * TOPK];      // (0.45*area bits, rank)
__device__ int          g_cellstart[BB * 257];
__device__ unsigned int g_mask[BB * TOPK * 32];

// ---------------- K0: zero hist ----------------
__global__ void k_zero() {
    g_hist[blockIdx.x * NBINS + threadIdx.x] = 0u;
}

// ---------------- K1: score + histogram ----------------
__global__ __launch_bounds__(256) void k_score(const float* __restrict__ x) {
    int b = blockIdx.y;
#pragma unroll
    for (int a = 0; a < 4; ++a) {
        int n = blockIdx.x * 1024 + a * 256 + threadIdx.x;
        if (n < NN) {
            const float4* row = (const float4*)(x + (long)(b * NN + n) * 16);
            float obj = row[1].x;   // col 4
            float cls = row[3].w;   // col 15
            float s = obj * cls;
            g_scores[b * NN + n] = s;
            if (s > CONF) {
                int bin = (int)((s - CONF) * (1024.0f / 0.75f));
                bin = min(bin, NBINS - 1);
                atomicAdd(&g_hist[b * NBINS + bin], 1u);
            }
        }
    }
}

// ---------------- K2: fused threshold + compact + sort + bin (1 block/image) ----------------
__global__ __launch_bounds__(1024) void k_topk(const float* __restrict__ x) {
    __shared__ unsigned int shist[NBINS];
    __shared__ unsigned long long sk[CAP];
    __shared__ int sT;
    __shared__ int counts[256];
    __shared__ int scanbuf[256];
    __shared__ int cstart[257];

    int b = blockIdx.x, t = threadIdx.x;
    int w = t >> 5, lane = t & 31;

    // ---- threshold: suffix scan of histogram ----
    shist[t] = g_hist[b * NBINS + t];
    if (t == 0) sT = 0;
    __syncthreads();
    for (int off = 1; off < NBINS; off <<= 1) {
        unsigned int v = (t + off < NBINS) ? shist[t + off] : 0u;
        __syncthreads();
        shist[t] += v;
        __syncthreads();
    }
    if (shist[t] >= TOPK) atomicMax(&sT, t);
    // ---- zero candidate keys ----
#pragma unroll
    for (int a = 0; a < 4; ++a) sk[t + a * 1024] = 0ULL;
    __syncthreads();

    // ---- compact: each warp owns anchors [w*CHUNK, (w+1)*CHUNK) -> segment sk[w*SEG..] ----
    {
        int T = sT;
        int base = w * CHUNK;
        int lim = min(base + CHUNK, NN);
        int cnt = 0;
        for (int it = 0; it < 25; ++it) {
            int n = base + it * 32 + lane;
            bool sel = false;
            float s = 0.0f;
            if (n < lim) {
                s = g_scores[b * NN + n];
                if (s > CONF) {
                    int bin = min((int)((s - CONF) * (1024.0f / 0.75f)), NBINS - 1);
                    sel = (bin >= T);
                }
            }
            unsigned int m = __ballot_sync(0xffffffffu, sel);
            if (sel) {
                int pos = cnt + __popc(m & ((1u << lane) - 1u));
                if (pos < SEG) {
                    sk[w * SEG + pos] =
                        ((unsigned long long)__float_as_uint(s) << 32) |
                        (unsigned long long)(0xFFFFFFFFu - (unsigned)n);
                }
            }
            cnt += __popc(m);
        }
    }
    __syncthreads();

    // ---- bitonic sort desc (4096 keys) ----
    for (int k = 2; k <= CAP; k <<= 1) {
        for (int j = k >> 1; j > 0; j >>= 1) {
            for (int e = t; e < CAP; e += 1024) {
                int ixj = e ^ j;
                if (ixj > e) {
                    unsigned long long a = sk[e], c = sk[ixj];
                    bool desc = ((e & k) == 0);
                    if (desc ? (a < c) : (a > c)) { sk[e] = c; sk[ixj] = a; }
                }
            }
            __syncthreads();
        }
    }

    // ---- extract top-1024, gather boxes ----
    unsigned long long key = sk[t];
    float sc = __uint_as_float((unsigned)(key >> 32));
    int idx = (key == 0ULL) ? 0 : (int)(0xFFFFFFFFu - (unsigned)(key & 0xFFFFFFFFu));
    if (idx < 0 || idx >= NN) idx = 0;
    g_topscore[b * TOPK + t] = (key == 0ULL) ? 0.0f : sc;
    g_topidx[b * TOPK + t] = idx;
    const float4* row = (const float4*)(x + (long)(b * NN + idx) * 16);
    float4 c0 = row[0];
    float hw = c0.z * 0.5f, hh = c0.w * 0.5f;
    float4 box = make_float4(c0.x - hw, c0.y - hh, c0.x + hw, c0.y + hh);
    g_boxes[b * TOPK + t] = box;
    float sv = 0.45f * (fmaxf(box.z - box.x, 0.0f) * fmaxf(box.w - box.y, 0.0f));
    int cellx = min(15, max(0, (int)(c0.x * 0.025f)));
    int celly = min(15, max(0, (int)(c0.y * 0.025f)));
    int cell = celly * 16 + cellx;

    // ---- spatial binning: count, scan, place ----
    if (t < 256) counts[t] = 0;
    __syncthreads();
    atomicAdd(&counts[cell], 1);
    __syncthreads();
    if (t < 256) scanbuf[t] = counts[t];
    __syncthreads();
    for (int off = 1; off < 256; off <<= 1) {
        int add = 0;
        if (t < 256 && t >= off) add = scanbuf[t - off];
        __syncthreads();
        if (t < 256) scanbuf[t] += add;
        __syncthreads();
    }
    if (t == 0) cstart[0] = 0;
    if (t < 256) { cstart[t + 1] = scanbuf[t]; counts[t] = (t == 0) ? 0 : scanbuf[t - 1]; }
    __syncthreads();
    {
        int pos = atomicAdd(&counts[cell], 1);
        g_sbox[b * TOPK + pos] = box;
        g_saux[b * TOPK + pos] = make_uint2(__float_as_uint(sv), (unsigned)t);
    }
    if (t < 257) g_cellstart[b * 257 + t] = cstart[t];
}

// ---------------- K3: sparse suppression-mask via spatial windows ----------------
// IoU>0 requires the partner's CENTER to lie within this box expanded by 64px
// (max half-size) + 0.5px f32-rounding slack. Windowed pairs get the proven
// f32 margin test; |diff|<=2e-5*s borderline resolved by IEEE __fdiv_rn.
// Each thread owns one spatial entry, accumulates its RANK-row privately in
// padded smem, writes the full 128B row once (no zeroing pass, no atomics).
__global__ __launch_bounds__(128) void k_pairs() {
    __shared__ float4       sbox[TOPK];     // 16KB
    __shared__ float        ssv[TOPK];      // 4KB
    __shared__ int          srank[TOPK];    // 4KB
    __shared__ int          cs[257];        // 1KB
    __shared__ unsigned int rows[128 * 36]; // 18KB, stride 36 = pad vs bank conflicts

    int b = blockIdx.y, t = threadIdx.x;
    int s = blockIdx.x * 128 + t;

    for (int e = t; e < TOPK; e += 128) {
        sbox[e] = g_sbox[b * TOPK + e];
        uint2 a = g_saux[b * TOPK + e];
        ssv[e] = __uint_as_float(a.x);
        srank[e] = (int)a.y;
    }
    for (int e = t; e < 257; e += 128) cs[e] = g_cellstart[b * 257 + e];
    __syncthreads();

    unsigned int* rowp = &rows[t * 36];
#pragma unroll
    for (int ww = 0; ww < 32; ++ww) rowp[ww] = 0u;

    float4 bs = sbox[s];
    float u = ssv[s];
    int rs = srank[s];

    int cl = max(0, (int)((bs.x - 64.5f) * 0.025f));
    int cr = min(15, (int)((bs.z + 64.5f) * 0.025f));
    int ct = max(0, (int)((bs.y - 64.5f) * 0.025f));
    int cb = min(15, (int)((bs.w + 64.5f) * 0.025f));

    for (int cy = ct; cy <= cb; ++cy) {
        int e0 = cs[cy * 16 + cl];
        int e1 = cs[cy * 16 + cr + 1];
        for (int e = e0; e < e1; ++e) {
            int re = srank[e];
            float4 be = sbox[e];
            float ix1 = fmaxf(bs.x, be.x), iy1 = fmaxf(bs.y, be.y);
            float ix2 = fminf(bs.z, be.z), iy2 = fminf(bs.w, be.w);
            float inter = fmaxf(ix2 - ix1, 0.0f) * fmaxf(iy2 - iy1, 0.0f);
            float sden = u + ssv[e];
            float diff = fmaf(1.45f, inter, -sden);
            bool bit;
            if (fabsf(diff) <= 2e-5f * sden) {   // rare: exact IEEE path
                float ai = fmaxf(bs.z - bs.x, 0.0f) * fmaxf(bs.w - bs.y, 0.0f);
                float aj = fmaxf(be.z - be.x, 0.0f) * fmaxf(be.w - be.y, 0.0f);
                float den = (ai + aj - inter) + 1e-9f;
                bit = (__fdiv_rn(inter, den) > IOUT);
            } else {
                bit = (diff > 0.0f);
            }
            if (bit && re > rs) rowp[re >> 5] |= 1u << (re & 31);
        }
    }

    unsigned int* orow = &g_mask[((long)(b * TOPK + rs)) * 32];
#pragma unroll
    for (int ww = 0; ww < 32; ++ww) orow[ww] = rowp[ww];
}

// ---------------- K4: sequential greedy scan (1 warp/image) + output ----------------
__global__ __launch_bounds__(1024) void k_scan_out(const float* __restrict__ x,
                                                   float* __restrict__ out) {
    __shared__ unsigned int validw[32];
    __shared__ unsigned int keepw[32];
    int b = blockIdx.x, t = threadIdx.x;
    float sc = g_topscore[b * TOPK + t];
    unsigned int vb = __ballot_sync(0xffffffffu, sc > 0.0f);
    if ((t & 31) == 0) validw[t >> 5] = vb;
    __syncthreads();

    if (t < 32) {
        int lane = t;
        unsigned int vw = validw[lane];
        const unsigned int* mrow = &g_mask[(long)(b * TOPK) * 32];
        unsigned int removed = 0u, kw = 0u;
        unsigned int buf[8];
#pragma unroll
        for (int p = 0; p < 8; ++p) buf[p] = mrow[p * 32 + lane];
#pragma unroll 8
        for (int i = 0; i < 1024; ++i) {
            unsigned int cur = buf[i & 7];
            int pre = i + 8;
            buf[i & 7] = (pre < 1024) ? mrow[pre * 32 + lane] : 0u;
            unsigned int ok = vw & ~removed;
            int wi = i >> 5;
            unsigned int okw = __shfl_sync(0xffffffffu, ok, wi);
            unsigned int kept = (okw >> (i & 31)) & 1u;
            removed |= kept ? cur : 0u;
            if (lane == wi) kw |= kept << (i & 31);
        }
        keepw[lane] = kw;
    }
    __syncthreads();

    unsigned int kept = (keepw[t >> 5] >> (t & 31)) & 1u;
    float4* orow = (float4*)(out + (long)(b * TOPK + t) * 16);
    if (kept) {
        int idx = g_topidx[b * TOPK + t];
        const float4* row = (const float4*)(x + (long)(b * NN + idx) * 16);
        float4 c0 = row[0], c1 = row[1], c2 = row[2], c3 = row[3];
        float hw = c0.z * 0.5f, hh = c0.w * 0.5f;
        orow[0] = make_float4(c0.x - hw, c0.y - hh, c0.x + hw, c0.y + hh);
        orow[1] = make_float4(sc, c1.y, c1.z, c1.w);
        orow[2] = c2;
        orow[3] = make_float4(c3.x, c3.y, c3.z, 0.0f);
    } else {
        float4 z = make_float4(0.0f, 0.0f, 0.0f, 0.0f);
        orow[0] = z; orow[1] = z; orow[2] = z; orow[3] = z;
    }
}

// ---------------- launch ----------------
extern "C" void kernel_launch(void* const* d_in, const int* in_sizes, int n_in,
                              void* d_out, int out_size) {
    const float* x = (const float*)d_in[0];
    float* out = (float*)d_out;
    (void)in_sizes; (void)n_in; (void)out_size;

    k_zero<<<BB, 1024>>>();
    {
        dim3 g((NN + 1023) / 1024, BB);
        k_score<<<g, 256>>>(x);
    }
    k_topk<<<BB, 1024>>>(x);
    {
        dim3 g(8, BB);
        k_pairs<<<g, 128>>>();
    }
    k_scan_out<<<BB, 1024>>>(x, out);
}

// round 5
// speedup vs baseline: 1.3332x; 1.1134x over previous
#include <cuda_runtime.h>
#include <cuda_bf16.h>

#define BB    64
#define NN    25200
#define TOPK  1024
#define CAP   2048
#define NBINS 1024
#define CONF  0.25f
#define IOUT  0.45f
#define CHUNK 788          // ceil(25200/32)

// ---------------- scratch (device globals: allocation-free) ----------------
__device__ float        g_scores[BB * NN];
__device__ unsigned int g_hist[BB * NBINS];
__device__ int          g_topidx[BB * TOPK];
__device__ float        g_topscore[BB * TOPK];
__device__ float4       g_sbox[BB * TOPK];      // cell-ordered boxes
__device__ uint2        g_saux[BB * TOPK];      // (0.45*area bits, rank)
__device__ int          g_cellstart[BB * 257];
__device__ unsigned int g_mask[BB * TOPK * 32];

// ---------------- K1: score + histogram ----------------
__global__ __launch_bounds__(256) void k_score(const float* __restrict__ x) {
    int b = blockIdx.y;
#pragma unroll
    for (int a = 0; a < 4; ++a) {
        int n = blockIdx.x * 1024 + a * 256 + threadIdx.x;
        if (n < NN) {
            const float4* row = (const float4*)(x + (long)(b * NN + n) * 16);
            float obj = row[1].x;   // col 4
            float cls = row[3].w;   // col 15
            float s = obj * cls;
            g_scores[b * NN + n] = s;
            if (s > CONF) {
                int bin = (int)((s - CONF) * (1024.0f / 0.75f));
                bin = min(bin, NBINS - 1);
                atomicAdd(&g_hist[b * NBINS + bin], 1u);
            }
        }
    }
}

// ---------------- K2: fused threshold + compact + sort(2048) + bin ----------------
__global__ __launch_bounds__(1024) void k_topk(const float* __restrict__ x) {
    __shared__ unsigned int shist[NBINS];
    __shared__ unsigned long long sk[CAP];
    __shared__ int sT;
    __shared__ int wcnt[32];
    __shared__ int woff[32];
    __shared__ int counts[256];
    __shared__ int scanbuf[256];
    __shared__ int cstart[257];

    int b = blockIdx.x, t = threadIdx.x;
    int w = t >> 5, lane = t & 31;

    // ---- threshold: suffix scan of histogram (and self-reset g_hist) ----
    shist[t] = g_hist[b * NBINS + t];
    g_hist[b * NBINS + t] = 0u;          // replay-safe reset
    if (t == 0) sT = 0;
    __syncthreads();
    for (int off = 1; off < NBINS; off <<= 1) {
        unsigned int v = (t + off < NBINS) ? shist[t + off] : 0u;
        __syncthreads();
        shist[t] += v;
        __syncthreads();
    }
    if (shist[t] >= TOPK) atomicMax(&sT, t);
    // zero candidate keys
    sk[t] = 0ULL; sk[t + 1024] = 0ULL;
    __syncthreads();

    // ---- compact pass 1: per-warp count ----
    int T = sT;
    int base = w * CHUNK;
    int lim = min(base + CHUNK, NN);
    int cnt = 0;
    for (int it = 0; it < 25; ++it) {
        int n = base + it * 32 + lane;
        bool sel = false;
        if (n < lim) {
            float s = g_scores[b * NN + n];
            if (s > CONF) {
                int bin = min((int)((s - CONF) * (1024.0f / 0.75f)), NBINS - 1);
                sel = (bin >= T);
            }
        }
        cnt += __popc(__ballot_sync(0xffffffffu, sel));
    }
    if (lane == 0) wcnt[w] = cnt;
    __syncthreads();
    // exclusive scan of 32 warp counts (warp 0)
    if (t < 32) {
        int v = wcnt[t];
        int p = v;
#pragma unroll
        for (int off = 1; off < 32; off <<= 1) {
            int y = __shfl_up_sync(0xffffffffu, p, off);
            if (t >= off) p += y;
        }
        woff[t] = p - v;   // exclusive
    }
    __syncthreads();

    // ---- compact pass 2: write at exact offsets (L1-hot re-read) ----
    {
        int off = woff[w];
        int run = 0;
        for (int it = 0; it < 25; ++it) {
            int n = base + it * 32 + lane;
            bool sel = false;
            float s = 0.0f;
            if (n < lim) {
                s = g_scores[b * NN + n];
                if (s > CONF) {
                    int bin = min((int)((s - CONF) * (1024.0f / 0.75f)), NBINS - 1);
                    sel = (bin >= T);
                }
            }
            unsigned int m = __ballot_sync(0xffffffffu, sel);
            if (sel) {
                int pos = off + run + __popc(m & ((1u << lane) - 1u));
                if (pos < CAP) {
                    sk[pos] = ((unsigned long long)__float_as_uint(s) << 32) |
                              (unsigned long long)(0xFFFFFFFFu - (unsigned)n);
                }
            }
            run += __popc(m);
        }
    }
    __syncthreads();

    // ---- bitonic sort desc (2048 keys, 1-2 elems/thread/pass) ----
    for (int k = 2; k <= CAP; k <<= 1) {
        for (int j = k >> 1; j > 0; j >>= 1) {
            for (int e = t; e < CAP; e += 1024) {
                int ixj = e ^ j;
                if (ixj > e) {
                    unsigned long long a = sk[e], c = sk[ixj];
                    bool desc = ((e & k) == 0);
                    if (desc ? (a < c) : (a > c)) { sk[e] = c; sk[ixj] = a; }
                }
            }
            __syncthreads();
        }
    }

    // ---- extract top-1024, gather boxes ----
    unsigned long long key = sk[t];
    float sc = __uint_as_float((unsigned)(key >> 32));
    int idx = (key == 0ULL) ? 0 : (int)(0xFFFFFFFFu - (unsigned)(key & 0xFFFFFFFFu));
    if (idx < 0 || idx >= NN) idx = 0;
    g_topscore[b * TOPK + t] = (key == 0ULL) ? 0.0f : sc;
    g_topidx[b * TOPK + t] = idx;
    const float4* row = (const float4*)(x + (long)(b * NN + idx) * 16);
    float4 c0 = row[0];
    float hw = c0.z * 0.5f, hh = c0.w * 0.5f;
    float4 box = make_float4(c0.x - hw, c0.y - hh, c0.x + hw, c0.y + hh);
    float sv = 0.45f * (fmaxf(box.z - box.x, 0.0f) * fmaxf(box.w - box.y, 0.0f));
    int cellx = min(15, max(0, (int)(c0.x * 0.025f)));
    int celly = min(15, max(0, (int)(c0.y * 0.025f)));
    int cell = celly * 16 + cellx;

    // ---- spatial binning: count, scan, place ----
    if (t < 256) counts[t] = 0;
    __syncthreads();
    atomicAdd(&counts[cell], 1);
    __syncthreads();
    if (t < 256) scanbuf[t] = counts[t];
    __syncthreads();
    for (int off = 1; off < 256; off <<= 1) {
        int add = 0;
        if (t < 256 && t >= off) add = scanbuf[t - off];
        __syncthreads();
        if (t < 256) scanbuf[t] += add;
        __syncthreads();
    }
    if (t == 0) cstart[0] = 0;
    if (t < 256) { cstart[t + 1] = scanbuf[t]; counts[t] = (t == 0) ? 0 : scanbuf[t - 1]; }
    __syncthreads();
    {
        int pos = atomicAdd(&counts[cell], 1);
        g_sbox[b * TOPK + pos] = box;
        g_saux[b * TOPK + pos] = make_uint2(__float_as_uint(sv), (unsigned)t);
    }
    if (t < 257) g_cellstart[b * 257 + t] = cstart[t];
}

// ---------------- K3: sparse suppression-mask via spatial windows ----------------
__global__ __launch_bounds__(128) void k_pairs() {
    __shared__ float4       sbox[TOPK];     // 16KB
    __shared__ uint2        sax[TOPK];      // 8KB: (sv bits, rank)
    __shared__ int          cs[257];        // 1KB
    __shared__ unsigned int rows[128 * 33]; // 16.5KB, stride 33: conflict-free

    int b = blockIdx.y, t = threadIdx.x;
    int s = blockIdx.x * 128 + t;

    for (int e = t; e < TOPK; e += 128) {
        sbox[e] = g_sbox[b * TOPK + e];
        sax[e]  = g_saux[b * TOPK + e];
    }
    for (int e = t; e < 257; e += 128) cs[e] = g_cellstart[b * 257 + e];
    __syncthreads();

    unsigned int* rowp = &rows[t * 33];
#pragma unroll
    for (int ww = 0; ww < 32; ++ww) rowp[ww] = 0u;

    float4 bs = sbox[s];
    uint2 axs = sax[s];
    float u = __uint_as_float(axs.x);
    int rs = (int)axs.y;

    int cl = max(0, (int)((bs.x - 64.5f) * 0.025f));
    int cr = min(15, (int)((bs.z + 64.5f) * 0.025f));
    int ct = max(0, (int)((bs.y - 64.5f) * 0.025f));
    int cb = min(15, (int)((bs.w + 64.5f) * 0.025f));

    for (int cy = ct; cy <= cb; ++cy) {
        int e0 = cs[cy * 16 + cl];
        int e1 = cs[cy * 16 + cr + 1];
#pragma unroll 2
        for (int e = e0; e < e1; ++e) {
            float4 be = sbox[e];
            uint2 axe = sax[e];
            float ix1 = fmaxf(bs.x, be.x), iy1 = fmaxf(bs.y, be.y);
            float ix2 = fminf(bs.z, be.z), iy2 = fminf(bs.w, be.w);
            float inter = fmaxf(ix2 - ix1, 0.0f) * fmaxf(iy2 - iy1, 0.0f);
            float sden = u + __uint_as_float(axe.x);
            float diff = fmaf(1.45f, inter, -sden);
            bool bit;
            if (fabsf(diff) <= 2e-5f * sden) {   // rare: exact IEEE path
                float ai = fmaxf(bs.z - bs.x, 0.0f) * fmaxf(bs.w - bs.y, 0.0f);
                float aj = fmaxf(be.z - be.x, 0.0f) * fmaxf(be.w - be.y, 0.0f);
                float den = (ai + aj - inter) + 1e-9f;
                bit = (__fdiv_rn(inter, den) > IOUT);
            } else {
                bit = (diff > 0.0f);
            }
            int re = (int)axe.y;
            if (bit && re > rs) rowp[re >> 5] |= 1u << (re & 31);
        }
    }

    unsigned int* orow = &g_mask[((long)(b * TOPK + rs)) * 32];
#pragma unroll
    for (int ww = 0; ww < 32; ++ww) orow[ww] = rowp[ww];
}

// ---------------- K4: sequential greedy scan (1 warp/image) + output ----------------
__global__ __launch_bounds__(1024) void k_scan_out(const float* __restrict__ x,
                                                   float* __restrict__ out) {
    __shared__ unsigned int validw[32];
    __shared__ unsigned int keepw[32];
    int b = blockIdx.x, t = threadIdx.x;
    float sc = g_topscore[b * TOPK + t];
    unsigned int vb = __ballot_sync(0xffffffffu, sc > 0.0f);
    if ((t & 31) == 0) validw[t >> 5] = vb;
    __syncthreads();

    if (t < 32) {
        int lane = t;
        unsigned int vw = validw[lane];
        const unsigned int* mrow = &g_mask[(long)(b * TOPK) * 32];
        unsigned int removed = 0u, kw = 0u;
        unsigned int buf[8];
#pragma unroll
        for (int p = 0; p < 8; ++p) buf[p] = mrow[p * 32 + lane];
#pragma unroll 8
        for (int i = 0; i < 1024; ++i) {
            unsigned int cur = buf[i & 7];
            int pre = i + 8;
            buf[i & 7] = (pre < 1024) ? mrow[pre * 32 + lane] : 0u;
            unsigned int ok = vw & ~removed;
            int wi = i >> 5;
            unsigned int okw = __shfl_sync(0xffffffffu, ok, wi);
            unsigned int kept = (okw >> (i & 31)) & 1u;
            removed |= kept ? cur : 0u;
            if (lane == wi) kw |= kept << (i & 31);
        }
        keepw[lane] = kw;
    }
    __syncthreads();

    unsigned int kept = (keepw[t >> 5] >> (t & 31)) & 1u;
    float4* orow = (float4*)(out + (long)(b * TOPK + t) * 16);
    if (kept) {
        int idx = g_topidx[b * TOPK + t];
        const float4* row = (const float4*)(x + (long)(b * NN + idx) * 16);
        float4 c0 = row[0], c1 = row[1], c2 = row[2], c3 = row[3];
        float hw = c0.z * 0.5f, hh = c0.w * 0.5f;
        orow[0] = make_float4(c0.x - hw, c0.y - hh, c0.x + hw, c0.y + hh);
        orow[1] = make_float4(sc, c1.y, c1.z, c1.w);
        orow[2] = c2;
        orow[3] = make_float4(c3.x, c3.y, c3.z, 0.0f);
    } else {
        float4 z = make_float4(0.0f, 0.0f, 0.0f, 0.0f);
        orow[0] = z; orow[1] = z; orow[2] = z; orow[3] = z;
    }
}

// ---------------- launch ----------------
extern "C" void kernel_launch(void* const* d_in, const int* in_sizes, int n_in,
                              void* d_out, int out_size) {
    const float* x = (const float*)d_in[0];
    float* out = (float*)d_out;
    (void)in_sizes; (void)n_in; (void)out_size;

    {
        dim3 g((NN + 1023) / 1024, BB);
        k_score<<<g, 256>>>(x);
    }
    k_topk<<<BB, 1024>>>(x);
    {
        dim3 g(8, BB);
        k_pairs<<<g, 128>>>();
    }
    k_scan_out<<<BB, 1024>>>(x, out);
}

// round 6
// speedup vs baseline: 2.0168x; 1.5128x over previous
#include <cuda_runtime.h>
#include <cuda_bf16.h>

#define BB    64
#define NN    25200
#define TOPK  1024
#define CAP   2048
#define NBINS 1024
#define CONF  0.25f
#define IOUT  0.45f
#define CHUNK 788          // ceil(25200/32)

// ---------------- scratch (device globals: allocation-free) ----------------
__device__ float        g_scores[BB * NN];
__device__ unsigned int g_hist[BB * NBINS];
__device__ int          g_topidx[BB * TOPK];
__device__ float        g_topscore[BB * TOPK];
__device__ float4       g_sbox[BB * TOPK];      // cell-ordered boxes
__device__ uint2        g_saux[BB * TOPK];      // (0.45*area bits, rank)
__device__ int          g_cellstart[BB * 257];
__device__ unsigned int g_mask[BB * TOPK * 32];
__device__ unsigned int g_wnz[BB * TOPK];       // per-rank word-presence mask

// ---------------- K1: score + histogram ----------------
__global__ __launch_bounds__(256) void k_score(const float* __restrict__ x) {
    int b = blockIdx.y;
#pragma unroll
    for (int a = 0; a < 4; ++a) {
        int n = blockIdx.x * 1024 + a * 256 + threadIdx.x;
        if (n < NN) {
            const float4* row = (const float4*)(x + (long)(b * NN + n) * 16);
            float obj = row[1].x;   // col 4
            float cls = row[3].w;   // col 15
            float s = obj * cls;
            g_scores[b * NN + n] = s;
            if (s > CONF) {
                int bin = (int)((s - CONF) * (1024.0f / 0.75f));
                bin = min(bin, NBINS - 1);
                atomicAdd(&g_hist[b * NBINS + bin], 1u);
            }
        }
    }
}

// ---------------- K2: fused threshold + compact + sort(2048) + bin ----------------
__global__ __launch_bounds__(1024) void k_topk(const float* __restrict__ x) {
    __shared__ unsigned int shist[NBINS];
    __shared__ unsigned long long sk[CAP];
    __shared__ int sT;
    __shared__ int wcnt[32];
    __shared__ int woff[32];
    __shared__ int counts[256];
    __shared__ int scanbuf[256];
    __shared__ int cstart[257];

    int b = blockIdx.x, t = threadIdx.x;
    int w = t >> 5, lane = t & 31;

    // ---- threshold: suffix scan of histogram (and self-reset g_hist) ----
    shist[t] = g_hist[b * NBINS + t];
    g_hist[b * NBINS + t] = 0u;          // replay-safe reset
    if (t == 0) sT = 0;
    __syncthreads();
    for (int off = 1; off < NBINS; off <<= 1) {
        unsigned int v = (t + off < NBINS) ? shist[t + off] : 0u;
        __syncthreads();
        shist[t] += v;
        __syncthreads();
    }
    if (shist[t] >= TOPK) atomicMax(&sT, t);
    sk[t] = 0ULL; sk[t + 1024] = 0ULL;
    __syncthreads();

    // ---- compact pass 1: per-warp count ----
    int T = sT;
    int base = w * CHUNK;
    int lim = min(base + CHUNK, NN);
    int cnt = 0;
    for (int it = 0; it < 25; ++it) {
        int n = base + it * 32 + lane;
        bool sel = false;
        if (n < lim) {
            float s = g_scores[b * NN + n];
            if (s > CONF) {
                int bin = min((int)((s - CONF) * (1024.0f / 0.75f)), NBINS - 1);
                sel = (bin >= T);
            }
        }
        cnt += __popc(__ballot_sync(0xffffffffu, sel));
    }
    if (lane == 0) wcnt[w] = cnt;
    __syncthreads();
    if (t < 32) {
        int v = wcnt[t];
        int p = v;
#pragma unroll
        for (int off = 1; off < 32; off <<= 1) {
            int y = __shfl_up_sync(0xffffffffu, p, off);
            if (t >= off) p += y;
        }
        woff[t] = p - v;
    }
    __syncthreads();

    // ---- compact pass 2: write at exact offsets ----
    {
        int off = woff[w];
        int run = 0;
        for (int it = 0; it < 25; ++it) {
            int n = base + it * 32 + lane;
            bool sel = false;
            float s = 0.0f;
            if (n < lim) {
                s = g_scores[b * NN + n];
                if (s > CONF) {
                    int bin = min((int)((s - CONF) * (1024.0f / 0.75f)), NBINS - 1);
                    sel = (bin >= T);
                }
            }
            unsigned int m = __ballot_sync(0xffffffffu, sel);
            if (sel) {
                int pos = off + run + __popc(m & ((1u << lane) - 1u));
                if (pos < CAP) {
                    sk[pos] = ((unsigned long long)__float_as_uint(s) << 32) |
                              (unsigned long long)(0xFFFFFFFFu - (unsigned)n);
                }
            }
            run += __popc(m);
        }
    }
    __syncthreads();

    // ---- bitonic sort desc (2048 keys) ----
    for (int k = 2; k <= CAP; k <<= 1) {
        for (int j = k >> 1; j > 0; j >>= 1) {
            for (int e = t; e < CAP; e += 1024) {
                int ixj = e ^ j;
                if (ixj > e) {
                    unsigned long long a = sk[e], c = sk[ixj];
                    bool desc = ((e & k) == 0);
                    if (desc ? (a < c) : (a > c)) { sk[e] = c; sk[ixj] = a; }
                }
            }
            __syncthreads();
        }
    }

    // ---- extract top-1024, gather boxes ----
    unsigned long long key = sk[t];
    float sc = __uint_as_float((unsigned)(key >> 32));
    int idx = (key == 0ULL) ? 0 : (int)(0xFFFFFFFFu - (unsigned)(key & 0xFFFFFFFFu));
    if (idx < 0 || idx >= NN) idx = 0;
    g_topscore[b * TOPK + t] = (key == 0ULL) ? 0.0f : sc;
    g_topidx[b * TOPK + t] = idx;
    const float4* row = (const float4*)(x + (long)(b * NN + idx) * 16);
    float4 c0 = row[0];
    float hw = c0.z * 0.5f, hh = c0.w * 0.5f;
    float4 box = make_float4(c0.x - hw, c0.y - hh, c0.x + hw, c0.y + hh);
    float sv = 0.45f * (fmaxf(box.z - box.x, 0.0f) * fmaxf(box.w - box.y, 0.0f));
    int cellx = min(15, max(0, (int)(c0.x * 0.025f)));
    int celly = min(15, max(0, (int)(c0.y * 0.025f)));
    int cell = celly * 16 + cellx;

    // ---- spatial binning ----
    if (t < 256) counts[t] = 0;
    __syncthreads();
    atomicAdd(&counts[cell], 1);
    __syncthreads();
    if (t < 256) scanbuf[t] = counts[t];
    __syncthreads();
    for (int off = 1; off < 256; off <<= 1) {
        int add = 0;
        if (t < 256 && t >= off) add = scanbuf[t - off];
        __syncthreads();
        if (t < 256) scanbuf[t] += add;
        __syncthreads();
    }
    if (t == 0) cstart[0] = 0;
    if (t < 256) { cstart[t + 1] = scanbuf[t]; counts[t] = (t == 0) ? 0 : scanbuf[t - 1]; }
    __syncthreads();
    {
        int pos = atomicAdd(&counts[cell], 1);
        g_sbox[b * TOPK + pos] = box;
        g_saux[b * TOPK + pos] = make_uint2(__float_as_uint(sv), (unsigned)t);
    }
    if (t < 257) g_cellstart[b * 257 + t] = cstart[t];
}

// ---------------- K3: sparse suppression-mask via spatial windows ----------------
__global__ __launch_bounds__(128) void k_pairs() {
    __shared__ float4       sbox[TOPK];
    __shared__ uint2        sax[TOPK];
    __shared__ int          cs[257];
    __shared__ unsigned int rows[128 * 33];

    int b = blockIdx.y, t = threadIdx.x;
    int s = blockIdx.x * 128 + t;

    for (int e = t; e < TOPK; e += 128) {
        sbox[e] = g_sbox[b * TOPK + e];
        sax[e]  = g_saux[b * TOPK + e];
    }
    for (int e = t; e < 257; e += 128) cs[e] = g_cellstart[b * 257 + e];
    __syncthreads();

    unsigned int* rowp = &rows[t * 33];
#pragma unroll
    for (int ww = 0; ww < 32; ++ww) rowp[ww] = 0u;

    float4 bs = sbox[s];
    uint2 axs = sax[s];
    float u = __uint_as_float(axs.x);
    int rs = (int)axs.y;

    int cl = max(0, (int)((bs.x - 64.5f) * 0.025f));
    int cr = min(15, (int)((bs.z + 64.5f) * 0.025f));
    int ct = max(0, (int)((bs.y - 64.5f) * 0.025f));
    int cb = min(15, (int)((bs.w + 64.5f) * 0.025f));

    for (int cy = ct; cy <= cb; ++cy) {
        int e0 = cs[cy * 16 + cl];
        int e1 = cs[cy * 16 + cr + 1];
#pragma unroll 2
        for (int e = e0; e < e1; ++e) {
            float4 be = sbox[e];
            uint2 axe = sax[e];
            float ix1 = fmaxf(bs.x, be.x), iy1 = fmaxf(bs.y, be.y);
            float ix2 = fminf(bs.z, be.z), iy2 = fminf(bs.w, be.w);
            float inter = fmaxf(ix2 - ix1, 0.0f) * fmaxf(iy2 - iy1, 0.0f);
            float sden = u + __uint_as_float(axe.x);
            float diff = fmaf(1.45f, inter, -sden);
            bool bit;
            if (fabsf(diff) <= 2e-5f * sden) {   // rare: exact IEEE path
                float ai = fmaxf(bs.z - bs.x, 0.0f) * fmaxf(bs.w - bs.y, 0.0f);
                float aj = fmaxf(be.z - be.x, 0.0f) * fmaxf(be.w - be.y, 0.0f);
                float den = (ai + aj - inter) + 1e-9f;
                bit = (__fdiv_rn(inter, den) > IOUT);
            } else {
                bit = (diff > 0.0f);
            }
            int re = (int)axe.y;
            if (bit && re > rs) rowp[re >> 5] |= 1u << (re & 31);
        }
    }

    // word-presence mask; only nonzero rows hit global memory
    unsigned int wm = 0u;
#pragma unroll
    for (int ww = 0; ww < 32; ++ww) wm |= (rowp[ww] != 0u) ? (1u << ww) : 0u;
    g_wnz[b * TOPK + rs] = wm;
    if (wm) {
        unsigned int* orow = &g_mask[((long)(b * TOPK + rs)) * 32];
#pragma unroll
        for (int ww = 0; ww < 32; ++ww) orow[ww] = rowp[ww];
    }
}

// ---------------- K4: sparse greedy scan + output ----------------
// Only ranks with nonzero suppression rows ("events") do work. Nonzero rows
// are compacted into dynamic smem; within a 32-rank word, rows only clear
// strictly-higher bits, so final alive == kept set after ascending events.
__global__ __launch_bounds__(1024) void k_scan_out(const float* __restrict__ x,
                                                   float* __restrict__ out) {
    extern __shared__ unsigned int srow[];          // [C*32], C = #nonzero rows
    __shared__ int          sslot[1024];
    __shared__ int          wcnt2[32], woff2[32];
    __shared__ unsigned int validw[32];
    __shared__ unsigned int keepw[32];

    int b = blockIdx.x, t = threadIdx.x;
    int w = t >> 5, lane = t & 31;

    float sc = g_topscore[b * TOPK + t];
    unsigned int vb = __ballot_sync(0xffffffffu, sc > 0.0f);
    if (lane == 0) validw[w] = vb;

    bool nzf = (g_wnz[b * TOPK + t] != 0u);
    unsigned int bm = __ballot_sync(0xffffffffu, nzf);
    if (lane == 0) wcnt2[w] = __popc(bm);
    __syncthreads();
    if (t < 32) {
        int v = wcnt2[t], p = v;
#pragma unroll
        for (int off = 1; off < 32; off <<= 1) {
            int y = __shfl_up_sync(0xffffffffu, p, off);
            if (t >= off) p += y;
        }
        woff2[t] = p - v;
    }
    __syncthreads();

    int slot = -1;
    if (nzf) {
        slot = woff2[w] + __popc(bm & ((1u << lane) - 1u));
        const uint4* src = (const uint4*)&g_mask[((long)(b * TOPK + t)) * 32];
        uint4* dst = (uint4*)&srow[slot * 32];
#pragma unroll
        for (int i = 0; i < 8; ++i) dst[i] = src[i];
    }
    sslot[t] = slot;
    __syncthreads();

    if (t < 32) {
        unsigned int removed = 0u;
        unsigned int vwl = validw[lane];
        for (int wi = 0; wi < 32; ++wi) {
            int slotj = sslot[wi * 32 + lane];                     // lane j: slot of rank wi*32+j
            unsigned int nzm = __ballot_sync(0xffffffffu, slotj >= 0);
            unsigned int alive = __shfl_sync(0xffffffffu, vwl & ~removed, wi);
            unsigned int evt = alive & nzm;
            while (evt) {
                int j = __ffs(evt) - 1;
                evt &= evt - 1u;
                int sj = __shfl_sync(0xffffffffu, slotj, j);
                unsigned int rw = srow[sj * 32 + lane];            // lane l: word l of row
                removed |= rw;
                alive &= ~__shfl_sync(0xffffffffu, rw, wi);
                evt &= alive;
            }
            if (lane == 0) keepw[wi] = alive;                      // final alive == kept bits
        }
    }
    __syncthreads();

    unsigned int kept = (keepw[t >> 5] >> (t & 31)) & 1u;
    float4* orow = (float4*)(out + (long)(b * TOPK + t) * 16);
    if (kept) {
        int idx = g_topidx[b * TOPK + t];
        const float4* row = (const float4*)(x + (long)(b * NN + idx) * 16);
        float4 c0 = row[0], c1 = row[1], c2 = row[2], c3 = row[3];
        float hw = c0.z * 0.5f, hh = c0.w * 0.5f;
        orow[0] = make_float4(c0.x - hw, c0.y - hh, c0.x + hw, c0.y + hh);
        orow[1] = make_float4(sc, c1.y, c1.z, c1.w);
        orow[2] = c2;
        orow[3] = make_float4(c3.x, c3.y, c3.z, 0.0f);
    } else {
        float4 z = make_float4(0.0f, 0.0f, 0.0f, 0.0f);
        orow[0] = z; orow[1] = z; orow[2] = z; orow[3] = z;
    }
}

// ---------------- launch ----------------
extern "C" void kernel_launch(void* const* d_in, const int* in_sizes, int n_in,
                              void* d_out, int out_size) {
    const float* x = (const float*)d_in[0];
    float* out = (float*)d_out;
    (void)in_sizes; (void)n_in; (void)out_size;

    // worst case: all 1024 rows nonzero -> 128KB dynamic smem (idempotent, capture-safe)
    cudaFuncSetAttribute(k_scan_out, cudaFuncAttributeMaxDynamicSharedMemorySize, 131072);

    {
        dim3 g((NN + 1023) / 1024, BB);
        k_score<<<g, 256>>>(x);
    }
    k_topk<<<BB, 1024>>>(x);
    {
        dim3 g(8, BB);
        k_pairs<<<g, 128>>>();
    }
    k_scan_out<<<BB, 1024, 131072>>>(x, out);
}

// round 7
// speedup vs baseline: 2.1829x; 1.0824x over previous
#include <cuda_runtime.h>
#include <cuda_bf16.h>

#define BB    64
#define NN    25200
#define TOPK  1024
#define CAP   2048
#define NBINS 1024
#define CONF  0.25f
#define IOUT  0.45f
#define CHUNK 788          // ceil(25200/32)

// ---------------- scratch (device globals: allocation-free) ----------------
__device__ float        g_scores[BB * NN];
__device__ unsigned int g_hist[BB * NBINS];
__device__ int          g_topidx[BB * TOPK];
__device__ float        g_topscore[BB * TOPK];
__device__ float4       g_sbox[BB * TOPK];      // cell-ordered boxes
__device__ uint2        g_saux[BB * TOPK];      // (0.45*area bits, rank)
__device__ int          g_cellstart[BB * 257];
__device__ unsigned int g_mask[BB * TOPK * 32];
__device__ unsigned int g_wnz[BB * TOPK];       // per-rank word-presence mask

// ---------------- K1: score + histogram ----------------
__global__ __launch_bounds__(256) void k_score(const float* __restrict__ x) {
    int b = blockIdx.y;
#pragma unroll
    for (int a = 0; a < 4; ++a) {
        int n = blockIdx.x * 1024 + a * 256 + threadIdx.x;
        if (n < NN) {
            const float4* row = (const float4*)(x + (long)(b * NN + n) * 16);
            float obj = row[1].x;   // col 4
            float cls = row[3].w;   // col 15
            float s = obj * cls;
            g_scores[b * NN + n] = s;
            if (s > CONF) {
                int bin = (int)((s - CONF) * (1024.0f / 0.75f));
                bin = min(bin, NBINS - 1);
                atomicAdd(&g_hist[b * NBINS + bin], 1u);
            }
        }
    }
}

// ---------------- K2: fused threshold + compact + sort(2048) + bin ----------------
__global__ __launch_bounds__(1024) void k_topk(const float* __restrict__ x) {
    __shared__ unsigned int shist[NBINS];
    __shared__ unsigned long long sk[CAP];
    __shared__ int sT;
    __shared__ int wcnt[32];
    __shared__ int woff[32];
    __shared__ int counts[256];
    __shared__ int scanbuf[256];
    __shared__ int cstart[257];

    int b = blockIdx.x, t = threadIdx.x;
    int w = t >> 5, lane = t & 31;

    // ---- threshold: suffix scan of histogram (and self-reset g_hist) ----
    shist[t] = g_hist[b * NBINS + t];
    g_hist[b * NBINS + t] = 0u;          // replay-safe reset
    if (t == 0) sT = 0;
    __syncthreads();
    for (int off = 1; off < NBINS; off <<= 1) {
        unsigned int v = (t + off < NBINS) ? shist[t + off] : 0u;
        __syncthreads();
        shist[t] += v;
        __syncthreads();
    }
    if (shist[t] >= TOPK) atomicMax(&sT, t);
    sk[t] = 0ULL; sk[t + 1024] = 0ULL;
    __syncthreads();

    // ---- compact pass 1: per-warp count ----
    int T = sT;
    int base = w * CHUNK;
    int lim = min(base + CHUNK, NN);
    int cnt = 0;
    for (int it = 0; it < 25; ++it) {
        int n = base + it * 32 + lane;
        bool sel = false;
        if (n < lim) {
            float s = g_scores[b * NN + n];
            if (s > CONF) {
                int bin = min((int)((s - CONF) * (1024.0f / 0.75f)), NBINS - 1);
                sel = (bin >= T);
            }
        }
        cnt += __popc(__ballot_sync(0xffffffffu, sel));
    }
    if (lane == 0) wcnt[w] = cnt;
    __syncthreads();
    if (t < 32) {
        int v = wcnt[t];
        int p = v;
#pragma unroll
        for (int off = 1; off < 32; off <<= 1) {
            int y = __shfl_up_sync(0xffffffffu, p, off);
            if (t >= off) p += y;
        }
        woff[t] = p - v;
    }
    __syncthreads();

    // ---- compact pass 2: write at exact offsets ----
    {
        int off = woff[w];
        int run = 0;
        for (int it = 0; it < 25; ++it) {
            int n = base + it * 32 + lane;
            bool sel = false;
            float s = 0.0f;
            if (n < lim) {
                s = g_scores[b * NN + n];
                if (s > CONF) {
                    int bin = min((int)((s - CONF) * (1024.0f / 0.75f)), NBINS - 1);
                    sel = (bin >= T);
                }
            }
            unsigned int m = __ballot_sync(0xffffffffu, sel);
            if (sel) {
                int pos = off + run + __popc(m & ((1u << lane) - 1u));
                if (pos < CAP) {
                    sk[pos] = ((unsigned long long)__float_as_uint(s) << 32) |
                              (unsigned long long)(0xFFFFFFFFu - (unsigned)n);
                }
            }
            run += __popc(m);
        }
    }
    __syncthreads();

    // ---- bitonic sort desc (2048 keys) ----
    for (int k = 2; k <= CAP; k <<= 1) {
        for (int j = k >> 1; j > 0; j >>= 1) {
            for (int e = t; e < CAP; e += 1024) {
                int ixj = e ^ j;
                if (ixj > e) {
                    unsigned long long a = sk[e], c = sk[ixj];
                    bool desc = ((e & k) == 0);
                    if (desc ? (a < c) : (a > c)) { sk[e] = c; sk[ixj] = a; }
                }
            }
            __syncthreads();
        }
    }

    // ---- extract top-1024, gather boxes ----
    unsigned long long key = sk[t];
    float sc = __uint_as_float((unsigned)(key >> 32));
    int idx = (key == 0ULL) ? 0 : (int)(0xFFFFFFFFu - (unsigned)(key & 0xFFFFFFFFu));
    if (idx < 0 || idx >= NN) idx = 0;
    g_topscore[b * TOPK + t] = (key == 0ULL) ? 0.0f : sc;
    g_topidx[b * TOPK + t] = idx;
    const float4* row = (const float4*)(x + (long)(b * NN + idx) * 16);
    float4 c0 = row[0];
    float hw = c0.z * 0.5f, hh = c0.w * 0.5f;
    float4 box = make_float4(c0.x - hw, c0.y - hh, c0.x + hw, c0.y + hh);
    float sv = 0.45f * (fmaxf(box.z - box.x, 0.0f) * fmaxf(box.w - box.y, 0.0f));
    int cellx = min(15, max(0, (int)(c0.x * 0.025f)));
    int celly = min(15, max(0, (int)(c0.y * 0.025f)));
    int cell = celly * 16 + cellx;

    // ---- spatial binning ----
    if (t < 256) counts[t] = 0;
    __syncthreads();
    atomicAdd(&counts[cell], 1);
    __syncthreads();
    if (t < 256) scanbuf[t] = counts[t];
    __syncthreads();
    for (int off = 1; off < 256; off <<= 1) {
        int add = 0;
        if (t < 256 && t >= off) add = scanbuf[t - off];
        __syncthreads();
        if (t < 256) scanbuf[t] += add;
        __syncthreads();
    }
    if (t == 0) cstart[0] = 0;
    if (t < 256) { cstart[t + 1] = scanbuf[t]; counts[t] = (t == 0) ? 0 : scanbuf[t - 1]; }
    __syncthreads();
    {
        int pos = atomicAdd(&counts[cell], 1);
        g_sbox[b * TOPK + pos] = box;
        g_saux[b * TOPK + pos] = make_uint2(__float_as_uint(sv), (unsigned)t);
    }
    if (t < 257) g_cellstart[b * 257 + t] = cstart[t];
}

// ---------------- K3: sparse suppression-mask, 4 threads per entry ----------------
// 512 threads/block: thread group of 4 (adjacent lanes) shares one spatial
// entry, striding its neighbor range by 4 and atomicOr-ing into the entry's
// shared row (commutative -> deterministic). 4x resident warps vs 1-thread/entry.
__global__ __launch_bounds__(512) void k_pairs() {
    __shared__ float4       sbox[TOPK];     // 16KB
    __shared__ uint2        sax[TOPK];      // 8KB
    __shared__ int          cs[257];        // 1KB
    __shared__ unsigned int rows[128 * 33]; // 16.5KB

    int b = blockIdx.y, t = threadIdx.x;
    int le = t >> 2;                  // local entry 0..127
    int q  = t & 3;                   // quarter
    int s  = blockIdx.x * 128 + le;   // global spatial entry

    for (int e = t; e < TOPK; e += 512) {
        sbox[e] = g_sbox[b * TOPK + e];
        sax[e]  = g_saux[b * TOPK + e];
    }
    for (int e = t; e < 257; e += 512) cs[e] = g_cellstart[b * 257 + e];
    __syncthreads();

    unsigned int* rowp = &rows[le * 33];
    for (int ww = q; ww < 32; ww += 4) rowp[ww] = 0u;
    __syncwarp();

    float4 bs = sbox[s];
    uint2 axs = sax[s];
    float u = __uint_as_float(axs.x);
    int rs = (int)axs.y;

    int cl = max(0, (int)((bs.x - 64.5f) * 0.025f));
    int cr = min(15, (int)((bs.z + 64.5f) * 0.025f));
    int ct = max(0, (int)((bs.y - 64.5f) * 0.025f));
    int cb = min(15, (int)((bs.w + 64.5f) * 0.025f));

    for (int cy = ct; cy <= cb; ++cy) {
        int e0 = cs[cy * 16 + cl];
        int e1 = cs[cy * 16 + cr + 1];
#pragma unroll 2
        for (int e = e0 + q; e < e1; e += 4) {
            float4 be = sbox[e];
            uint2 axe = sax[e];
            float ix1 = fmaxf(bs.x, be.x), iy1 = fmaxf(bs.y, be.y);
            float ix2 = fminf(bs.z, be.z), iy2 = fminf(bs.w, be.w);
            float inter = fmaxf(ix2 - ix1, 0.0f) * fmaxf(iy2 - iy1, 0.0f);
            float sden = u + __uint_as_float(axe.x);
            float diff = fmaf(1.45f, inter, -sden);
            bool bit;
            if (fabsf(diff) <= 2e-5f * sden) {   // rare: exact IEEE path
                float ai = fmaxf(bs.z - bs.x, 0.0f) * fmaxf(bs.w - bs.y, 0.0f);
                float aj = fmaxf(be.z - be.x, 0.0f) * fmaxf(be.w - be.y, 0.0f);
                float den = (ai + aj - inter) + 1e-9f;
                bit = (__fdiv_rn(inter, den) > IOUT);
            } else {
                bit = (diff > 0.0f);
            }
            int re = (int)axe.y;
            if (bit && re > rs) atomicOr(&rowp[re >> 5], 1u << (re & 31));
        }
    }
    __syncwarp();

    if (q == 0) {
        unsigned int wm = 0u;
#pragma unroll
        for (int ww = 0; ww < 32; ++ww) wm |= (rowp[ww] != 0u) ? (1u << ww) : 0u;
        g_wnz[b * TOPK + rs] = wm;
        if (wm) {
            unsigned int* orow = &g_mask[((long)(b * TOPK + rs)) * 32];
#pragma unroll
            for (int ww = 0; ww < 32; ++ww) orow[ww] = rowp[ww];
        }
    }
}

// ---------------- K4: sparse greedy scan + output ----------------
__global__ __launch_bounds__(1024) void k_scan_out(const float* __restrict__ x,
                                                   float* __restrict__ out) {
    extern __shared__ unsigned int srow[];          // [C*32]
    __shared__ int          sslot[1024];
    __shared__ int          wcnt2[32], woff2[32];
    __shared__ unsigned int validw[32];
    __shared__ unsigned int keepw[32];

    int b = blockIdx.x, t = threadIdx.x;
    int w = t >> 5, lane = t & 31;

    float sc = g_topscore[b * TOPK + t];
    unsigned int vb = __ballot_sync(0xffffffffu, sc > 0.0f);
    if (lane == 0) validw[w] = vb;

    bool nzf = (g_wnz[b * TOPK + t] != 0u);
    unsigned int bm = __ballot_sync(0xffffffffu, nzf);
    if (lane == 0) wcnt2[w] = __popc(bm);
    __syncthreads();
    if (t < 32) {
        int v = wcnt2[t], p = v;
#pragma unroll
        for (int off = 1; off < 32; off <<= 1) {
            int y = __shfl_up_sync(0xffffffffu, p, off);
            if (t >= off) p += y;
        }
        woff2[t] = p - v;
    }
    __syncthreads();

    int slot = -1;
    if (nzf) {
        slot = woff2[w] + __popc(bm & ((1u << lane) - 1u));
        const uint4* src = (const uint4*)&g_mask[((long)(b * TOPK + t)) * 32];
        uint4* dst = (uint4*)&srow[slot * 32];
#pragma unroll
        for (int i = 0; i < 8; ++i) dst[i] = src[i];
    }
    sslot[t] = slot;
    __syncthreads();

    if (t < 32) {
        unsigned int removed = 0u;
        unsigned int vwl = validw[lane];
        for (int wi = 0; wi < 32; ++wi) {
            int slotj = sslot[wi * 32 + lane];
            unsigned int nzm = __ballot_sync(0xffffffffu, slotj >= 0);
            unsigned int alive = __shfl_sync(0xffffffffu, vwl & ~removed, wi);
            unsigned int evt = alive & nzm;
            while (evt) {
                int j = __ffs(evt) - 1;
                evt &= evt - 1u;
                int sj = __shfl_sync(0xffffffffu, slotj, j);
                unsigned int rw = srow[sj * 32 + lane];
                removed |= rw;
                alive &= ~__shfl_sync(0xffffffffu, rw, wi);
                evt &= alive;
            }
            if (lane == 0) keepw[wi] = alive;
        }
    }
    __syncthreads();

    unsigned int kept = (keepw[t >> 5] >> (t & 31)) & 1u;
    float4* orow = (float4*)(out + (long)(b * TOPK + t) * 16);
    if (kept) {
        int idx = g_topidx[b * TOPK + t];
        const float4* row = (const float4*)(x + (long)(b * NN + idx) * 16);
        float4 c0 = row[0], c1 = row[1], c2 = row[2], c3 = row[3];
        float hw = c0.z * 0.5f, hh = c0.w * 0.5f;
        orow[0] = make_float4(c0.x - hw, c0.y - hh, c0.x + hw, c0.y + hh);
        orow[1] = make_float4(sc, c1.y, c1.z, c1.w);
        orow[2] = c2;
        orow[3] = make_float4(c3.x, c3.y, c3.z, 0.0f);
    } else {
        float4 z = make_float4(0.0f, 0.0f, 0.0f, 0.0f);
        orow[0] = z; orow[1] = z; orow[2] = z; orow[3] = z;
    }
}

// ---------------- launch ----------------
extern "C" void kernel_launch(void* const* d_in, const int* in_sizes, int n_in,
                              void* d_out, int out_size) {
    const float* x = (const float*)d_in[0];
    float* out = (float*)d_out;
    (void)in_sizes; (void)n_in; (void)out_size;

    cudaFuncSetAttribute(k_scan_out, cudaFuncAttributeMaxDynamicSharedMemorySize, 131072);

    {
        dim3 g((NN + 1023) / 1024, BB);
        k_score<<<g, 256>>>(x);
    }
    k_topk<<<BB, 1024>>>(x);
    {
        dim3 g(8, BB);
        k_pairs<<<g, 512>>>();
    }
    k_scan_out<<<BB, 1024, 131072>>>(x, out);
}

// round 8
// speedup vs baseline: 2.2508x; 1.0311x over previous
#include <cuda_runtime.h>
#include <cuda_bf16.h>

#define BB    64
#define NN    25200
#define TOPK  1024
#define CAP   2048
#define NBINS 1024
#define CONF  0.25f
#define IOUT  0.45f
#define CHUNK 788          // ceil(25200/32)
#define RSTR  36           // srow stride (words): bank-conflict-free + 16B aligned

// ---------------- scratch (device globals: allocation-free) ----------------
__device__ float        g_scores[BB * NN];
__device__ unsigned int g_hist[BB * NBINS];
__device__ int          g_topidx[BB * TOPK];
__device__ float        g_topscore[BB * TOPK];
__device__ float4       g_sbox[BB * TOPK];      // cell-ordered boxes
__device__ uint2        g_saux[BB * TOPK];      // (0.45*area bits, rank)
__device__ int          g_cellstart[BB * 257];
__device__ unsigned int g_mask[BB * TOPK * 32];
__device__ unsigned int g_wnz[BB * TOPK];       // per-rank nonzero-row flag

// ---------------- K1: score + histogram ----------------
__global__ __launch_bounds__(256) void k_score(const float* __restrict__ x) {
    int b = blockIdx.y;
#pragma unroll
    for (int a = 0; a < 4; ++a) {
        int n = blockIdx.x * 1024 + a * 256 + threadIdx.x;
        if (n < NN) {
            const float4* row = (const float4*)(x + (long)(b * NN + n) * 16);
            float obj = row[1].x;   // col 4
            float cls = row[3].w;   // col 15
            float s = obj * cls;
            g_scores[b * NN + n] = s;
            if (s > CONF) {
                int bin = (int)((s - CONF) * (1024.0f / 0.75f));
                bin = min(bin, NBINS - 1);
                atomicAdd(&g_hist[b * NBINS + bin], 1u);
            }
        }
    }
}

// ---------------- K2: fused threshold + compact + sort(2048) + bin ----------------
__global__ __launch_bounds__(1024) void k_topk(const float* __restrict__ x) {
    __shared__ unsigned int shist[NBINS];
    __shared__ unsigned long long sk[CAP];
    __shared__ int sT;
    __shared__ int wcnt[32];
    __shared__ int woff[32];
    __shared__ int counts[256];
    __shared__ int scanbuf[256];
    __shared__ int cstart[257];

    int b = blockIdx.x, t = threadIdx.x;
    int w = t >> 5, lane = t & 31;

    // ---- threshold: suffix scan of histogram (and self-reset g_hist) ----
    shist[t] = g_hist[b * NBINS + t];
    g_hist[b * NBINS + t] = 0u;          // replay-safe reset
    if (t == 0) sT = 0;
    __syncthreads();
    for (int off = 1; off < NBINS; off <<= 1) {
        unsigned int v = (t + off < NBINS) ? shist[t + off] : 0u;
        __syncthreads();
        shist[t] += v;
        __syncthreads();
    }
    if (shist[t] >= TOPK) atomicMax(&sT, t);
    sk[t] = 0ULL; sk[t + 1024] = 0ULL;
    __syncthreads();

    // ---- compact pass 1: per-warp count ----
    int T = sT;
    int base = w * CHUNK;
    int lim = min(base + CHUNK, NN);
    int cnt = 0;
    for (int it = 0; it < 25; ++it) {
        int n = base + it * 32 + lane;
        bool sel = false;
        if (n < lim) {
            float s = g_scores[b * NN + n];
            if (s > CONF) {
                int bin = min((int)((s - CONF) * (1024.0f / 0.75f)), NBINS - 1);
                sel = (bin >= T);
            }
        }
        cnt += __popc(__ballot_sync(0xffffffffu, sel));
    }
    if (lane == 0) wcnt[w] = cnt;
    __syncthreads();
    if (t < 32) {
        int v = wcnt[t];
        int p = v;
#pragma unroll
        for (int off = 1; off < 32; off <<= 1) {
            int y = __shfl_up_sync(0xffffffffu, p, off);
            if (t >= off) p += y;
        }
        woff[t] = p - v;
    }
    __syncthreads();

    // ---- compact pass 2: write at exact offsets ----
    {
        int off = woff[w];
        int run = 0;
        for (int it = 0; it < 25; ++it) {
            int n = base + it * 32 + lane;
            bool sel = false;
            float s = 0.0f;
            if (n < lim) {
                s = g_scores[b * NN + n];
                if (s > CONF) {
                    int bin = min((int)((s - CONF) * (1024.0f / 0.75f)), NBINS - 1);
                    sel = (bin >= T);
                }
            }
            unsigned int m = __ballot_sync(0xffffffffu, sel);
            if (sel) {
                int pos = off + run + __popc(m & ((1u << lane) - 1u));
                if (pos < CAP) {
                    sk[pos] = ((unsigned long long)__float_as_uint(s) << 32) |
                              (unsigned long long)(0xFFFFFFFFu - (unsigned)n);
                }
            }
            run += __popc(m);
        }
    }
    __syncthreads();

    // ---- bitonic sort desc (2048 keys) ----
    for (int k = 2; k <= CAP; k <<= 1) {
        for (int j = k >> 1; j > 0; j >>= 1) {
            for (int e = t; e < CAP; e += 1024) {
                int ixj = e ^ j;
                if (ixj > e) {
                    unsigned long long a = sk[e], c = sk[ixj];
                    bool desc = ((e & k) == 0);
                    if (desc ? (a < c) : (a > c)) { sk[e] = c; sk[ixj] = a; }
                }
            }
            __syncthreads();
        }
    }

    // ---- extract top-1024, gather boxes ----
    unsigned long long key = sk[t];
    float sc = __uint_as_float((unsigned)(key >> 32));
    int idx = (key == 0ULL) ? 0 : (int)(0xFFFFFFFFu - (unsigned)(key & 0xFFFFFFFFu));
    if (idx < 0 || idx >= NN) idx = 0;
    g_topscore[b * TOPK + t] = (key == 0ULL) ? 0.0f : sc;
    g_topidx[b * TOPK + t] = idx;
    const float4* row = (const float4*)(x + (long)(b * NN + idx) * 16);
    float4 c0 = row[0];
    float hw = c0.z * 0.5f, hh = c0.w * 0.5f;
    float4 box = make_float4(c0.x - hw, c0.y - hh, c0.x + hw, c0.y + hh);
    float sv = 0.45f * (fmaxf(box.z - box.x, 0.0f) * fmaxf(box.w - box.y, 0.0f));
    int cellx = min(15, max(0, (int)(c0.x * 0.025f)));
    int celly = min(15, max(0, (int)(c0.y * 0.025f)));
    int cell = celly * 16 + cellx;

    // ---- spatial binning ----
    if (t < 256) counts[t] = 0;
    __syncthreads();
    atomicAdd(&counts[cell], 1);
    __syncthreads();
    if (t < 256) scanbuf[t] = counts[t];
    __syncthreads();
    for (int off = 1; off < 256; off <<= 1) {
        int add = 0;
        if (t < 256 && t >= off) add = scanbuf[t - off];
        __syncthreads();
        if (t < 256) scanbuf[t] += add;
        __syncthreads();
    }
    if (t == 0) cstart[0] = 0;
    if (t < 256) { cstart[t + 1] = scanbuf[t]; counts[t] = (t == 0) ? 0 : scanbuf[t - 1]; }
    __syncthreads();
    {
        int pos = atomicAdd(&counts[cell], 1);
        g_sbox[b * TOPK + pos] = box;
        g_saux[b * TOPK + pos] = make_uint2(__float_as_uint(sv), (unsigned)t);
    }
    if (t < 257) g_cellstart[b * 257 + t] = cstart[t];
}

// ---------------- K3: sparse suppression-mask, 4 threads per entry ----------------
__global__ __launch_bounds__(512) void k_pairs() {
    __shared__ float4       sbox[TOPK];     // 16KB
    __shared__ uint2        sax[TOPK];      // 8KB
    __shared__ int          cs[257];        // 1KB
    __shared__ unsigned int rows[128 * 33]; // 16.5KB

    int b = blockIdx.y, t = threadIdx.x;
    int le = t >> 2;                  // local entry 0..127
    int q  = t & 3;                   // quarter
    int s  = blockIdx.x * 128 + le;   // global spatial entry

    for (int e = t; e < TOPK; e += 512) {
        sbox[e] = g_sbox[b * TOPK + e];
        sax[e]  = g_saux[b * TOPK + e];
    }
    for (int e = t; e < 257; e += 512) cs[e] = g_cellstart[b * 257 + e];
    __syncthreads();

    unsigned int* rowp = &rows[le * 33];
    for (int ww = q; ww < 32; ww += 4) rowp[ww] = 0u;
    __syncwarp();

    float4 bs = sbox[s];
    uint2 axs = sax[s];
    float u = __uint_as_float(axs.x);
    int rs = (int)axs.y;

    int cl = max(0, (int)((bs.x - 64.5f) * 0.025f));
    int cr = min(15, (int)((bs.z + 64.5f) * 0.025f));
    int ct = max(0, (int)((bs.y - 64.5f) * 0.025f));
    int cb = min(15, (int)((bs.w + 64.5f) * 0.025f));

    for (int cy = ct; cy <= cb; ++cy) {
        int e0 = cs[cy * 16 + cl];
        int e1 = cs[cy * 16 + cr + 1];
#pragma unroll 2
        for (int e = e0 + q; e < e1; e += 4) {
            float4 be = sbox[e];
            uint2 axe = sax[e];
            float ix1 = fmaxf(bs.x, be.x), iy1 = fmaxf(bs.y, be.y);
            float ix2 = fminf(bs.z, be.z), iy2 = fminf(bs.w, be.w);
            float inter = fmaxf(ix2 - ix1, 0.0f) * fmaxf(iy2 - iy1, 0.0f);
            float sden = u + __uint_as_float(axe.x);
            float diff = fmaf(1.45f, inter, -sden);
            bool bit;
            if (fabsf(diff) <= 2e-5f * sden) {   // rare: exact IEEE path
                float ai = fmaxf(bs.z - bs.x, 0.0f) * fmaxf(bs.w - bs.y, 0.0f);
                float aj = fmaxf(be.z - be.x, 0.0f) * fmaxf(be.w - be.y, 0.0f);
                float den = (ai + aj - inter) + 1e-9f;
                bit = (__fdiv_rn(inter, den) > IOUT);
            } else {
                bit = (diff > 0.0f);
            }
            int re = (int)axe.y;
            if (bit && re > rs) atomicOr(&rowp[re >> 5], 1u << (re & 31));
        }
    }
    __syncwarp();

    if (q == 0) {
        unsigned int wm = 0u;
#pragma unroll
        for (int ww = 0; ww < 32; ++ww) wm |= (rowp[ww] != 0u) ? (1u << ww) : 0u;
        g_wnz[b * TOPK + rs] = wm;
        if (wm) {
            unsigned int* orow = &g_mask[((long)(b * TOPK + rs)) * 32];
#pragma unroll
            for (int ww = 0; ww < 32; ++ww) orow[ww] = rowp[ww];
        }
    }
}

// ---------------- K4: rank-indexed sparse greedy scan + output ----------------
// Rows stored rank-indexed in dynamic smem (stride RSTR: conflict-free,
// 16B-aligned). Event words are warp-uniform -> per-event critical path is
// just LDS(row) + one shfl. Rows without the har bit are never read, so no
// zero-fill is needed.
__global__ __launch_bounds__(1024) void k_scan_out(const float* __restrict__ x,
                                                   float* __restrict__ out) {
    extern __shared__ unsigned int srow[];          // [TOPK * RSTR]
    __shared__ unsigned int validw[32];
    __shared__ unsigned int harw[32];
    __shared__ unsigned int keepw[32];

    int b = blockIdx.x, t = threadIdx.x;
    int w = t >> 5, lane = t & 31;

    float sc = g_topscore[b * TOPK + t];
    unsigned int vb = __ballot_sync(0xffffffffu, sc > 0.0f);
    if (lane == 0) validw[w] = vb;

    bool nzf = (g_wnz[b * TOPK + t] != 0u);
    unsigned int hb = __ballot_sync(0xffffffffu, nzf);
    if (lane == 0) harw[w] = hb;

    if (nzf) {
        const uint4* src = (const uint4*)&g_mask[((long)(b * TOPK + t)) * 32];
        uint4* dst = (uint4*)&srow[t * RSTR];
#pragma unroll
        for (int i = 0; i < 8; ++i) dst[i] = src[i];
    }
    __syncthreads();

    if (t < 32) {
        unsigned int removed = 0u;
        unsigned int vwl = validw[lane];
        unsigned int har = harw[lane];
        for (int wi = 0; wi < 32; ++wi) {
            unsigned int alive = __shfl_sync(0xffffffffu, vwl & ~removed, wi);
            unsigned int evt = alive & __shfl_sync(0xffffffffu, har, wi);
            while (evt) {
                int j = __ffs(evt) - 1;            // warp-uniform
                evt &= evt - 1u;
                unsigned int rw = srow[((wi << 5) + j) * RSTR + lane];
                removed |= rw;
                alive &= ~__shfl_sync(0xffffffffu, rw, wi);
                evt &= alive;
            }
            if (lane == 0) keepw[wi] = alive;
        }
    }
    __syncthreads();

    unsigned int kept = (keepw[t >> 5] >> (t & 31)) & 1u;
    float4* orow = (float4*)(out + (long)(b * TOPK + t) * 16);
    if (kept) {
        int idx = g_topidx[b * TOPK + t];
        const float4* row = (const float4*)(x + (long)(b * NN + idx) * 16);
        float4 c0 = row[0], c1 = row[1], c2 = row[2], c3 = row[3];
        float hw = c0.z * 0.5f, hh = c0.w * 0.5f;
        orow[0] = make_float4(c0.x - hw, c0.y - hh, c0.x + hw, c0.y + hh);
        orow[1] = make_float4(sc, c1.y, c1.z, c1.w);
        orow[2] = c2;
        orow[3] = make_float4(c3.x, c3.y, c3.z, 0.0f);
    } else {
        float4 z = make_float4(0.0f, 0.0f, 0.0f, 0.0f);
        orow[0] = z; orow[1] = z; orow[2] = z; orow[3] = z;
    }
}

// ---------------- launch ----------------
extern "C" void kernel_launch(void* const* d_in, const int* in_sizes, int n_in,
                              void* d_out, int out_size) {
    const float* x = (const float*)d_in[0];
    float* out = (float*)d_out;
    (void)in_sizes; (void)n_in; (void)out_size;

    const int scan_smem = TOPK * RSTR * 4;   // 147456 bytes
    cudaFuncSetAttribute(k_scan_out, cudaFuncAttributeMaxDynamicSharedMemorySize, scan_smem);

    {
        dim3 g((NN + 1023) / 1024, BB);
        k_score<<<g, 256>>>(x);
    }
    k_topk<<<BB, 1024>>>(x);
    {
        dim3 g(8, BB);
        k_pairs<<<g, 512>>>();
    }
    k_scan_out<<<BB, 1024, scan_smem>>>(x, out);
}

// round 9
// speedup vs baseline: 2.3043x; 1.0238x over previous
#include <cuda_runtime.h>
#include <cuda_bf16.h>

#define BB    64
#define NN    25200
#define TOPK  1024
#define CAP   2048
#define NBINS 1024
#define CONF  0.25f
#define IOUT  0.45f
#define CHUNK 788          // ceil(25200/32)
#define RSTR  36           // srow stride (words): bank-conflict-free + 16B aligned

// ---------------- scratch (device globals: allocation-free) ----------------
__device__ float        g_scores[BB * NN];
__device__ unsigned int g_hist[BB * NBINS];
__device__ int          g_topidx[BB * TOPK];
__device__ float        g_topscore[BB * TOPK];
__device__ float4       g_sbox[BB * TOPK];      // cell-ordered boxes
__device__ uint2        g_saux[BB * TOPK];      // (0.45*area bits, rank)
__device__ int          g_cellstart[BB * 257];
__device__ unsigned int g_mask[BB * TOPK * 32];
__device__ unsigned int g_wnz[BB * TOPK];       // per-rank nonzero-row flag

// ---------------- K1: score + histogram ----------------
__global__ __launch_bounds__(256) void k_score(const float* __restrict__ x) {
    int b = blockIdx.y;
#pragma unroll
    for (int a = 0; a < 4; ++a) {
        int n = blockIdx.x * 1024 + a * 256 + threadIdx.x;
        if (n < NN) {
            const float* row = x + (long)(b * NN + n) * 16;
            float obj = __ldg(row + 4);
            float cls = __ldg(row + 15);
            float s = obj * cls;
            g_scores[b * NN + n] = s;
            if (s > CONF) {
                int bin = (int)((s - CONF) * (1024.0f / 0.75f));
                bin = min(bin, NBINS - 1);
                atomicAdd(&g_hist[b * NBINS + bin], 1u);
            }
        }
    }
}

// ---------------- K2: fused threshold + compact + sort(2048) + bin ----------------
__global__ __launch_bounds__(1024) void k_topk(const float* __restrict__ x) {
    __shared__ unsigned int shist[NBINS];
    __shared__ unsigned long long sk[CAP];
    __shared__ int sT;
    __shared__ int wcnt[32];
    __shared__ int woff[32];
    __shared__ int counts[256];
    __shared__ int scanbuf[256];
    __shared__ int cstart[257];

    int b = blockIdx.x, t = threadIdx.x;
    int w = t >> 5, lane = t & 31;

    // ---- threshold: suffix scan of histogram (and self-reset g_hist) ----
    shist[t] = g_hist[b * NBINS + t];
    g_hist[b * NBINS + t] = 0u;          // replay-safe reset
    if (t == 0) sT = 0;
    __syncthreads();
    for (int off = 1; off < NBINS; off <<= 1) {
        unsigned int v = (t + off < NBINS) ? shist[t + off] : 0u;
        __syncthreads();
        shist[t] += v;
        __syncthreads();
    }
    if (shist[t] >= TOPK) atomicMax(&sT, t);
    sk[t] = 0ULL; sk[t + 1024] = 0ULL;
    __syncthreads();

    // ---- compact pass 1: per-warp count ----
    int T = sT;
    int base = w * CHUNK;
    int lim = min(base + CHUNK, NN);
    int cnt = 0;
    for (int it = 0; it < 25; ++it) {
        int n = base + it * 32 + lane;
        bool sel = false;
        if (n < lim) {
            float s = g_scores[b * NN + n];
            if (s > CONF) {
                int bin = min((int)((s - CONF) * (1024.0f / 0.75f)), NBINS - 1);
                sel = (bin >= T);
            }
        }
        cnt += __popc(__ballot_sync(0xffffffffu, sel));
    }
    if (lane == 0) wcnt[w] = cnt;
    __syncthreads();
    if (t < 32) {
        int v = wcnt[t];
        int p = v;
#pragma unroll
        for (int off = 1; off < 32; off <<= 1) {
            int y = __shfl_up_sync(0xffffffffu, p, off);
            if (t >= off) p += y;
        }
        woff[t] = p - v;
    }
    __syncthreads();

    // ---- compact pass 2: write at exact offsets ----
    {
        int off = woff[w];
        int run = 0;
        for (int it = 0; it < 25; ++it) {
            int n = base + it * 32 + lane;
            bool sel = false;
            float s = 0.0f;
            if (n < lim) {
                s = g_scores[b * NN + n];
                if (s > CONF) {
                    int bin = min((int)((s - CONF) * (1024.0f / 0.75f)), NBINS - 1);
                    sel = (bin >= T);
                }
            }
            unsigned int m = __ballot_sync(0xffffffffu, sel);
            if (sel) {
                int pos = off + run + __popc(m & ((1u << lane) - 1u));
                if (pos < CAP) {
                    sk[pos] = ((unsigned long long)__float_as_uint(s) << 32) |
                              (unsigned long long)(0xFFFFFFFFu - (unsigned)n);
                }
            }
            run += __popc(m);
        }
    }
    __syncthreads();

    // ---- bitonic sort desc (2048 keys) ----
    for (int k = 2; k <= CAP; k <<= 1) {
        for (int j = k >> 1; j > 0; j >>= 1) {
            for (int e = t; e < CAP; e += 1024) {
                int ixj = e ^ j;
                if (ixj > e) {
                    unsigned long long a = sk[e], c = sk[ixj];
                    bool desc = ((e & k) == 0);
                    if (desc ? (a < c) : (a > c)) { sk[e] = c; sk[ixj] = a; }
                }
            }
            __syncthreads();
        }
    }

    // ---- extract top-1024, gather boxes ----
    unsigned long long key = sk[t];
    float sc = __uint_as_float((unsigned)(key >> 32));
    int idx = (key == 0ULL) ? 0 : (int)(0xFFFFFFFFu - (unsigned)(key & 0xFFFFFFFFu));
    if (idx < 0 || idx >= NN) idx = 0;
    g_topscore[b * TOPK + t] = (key == 0ULL) ? 0.0f : sc;
    g_topidx[b * TOPK + t] = idx;
    const float4* row = (const float4*)(x + (long)(b * NN + idx) * 16);
    float4 c0 = row[0];
    float hw = c0.z * 0.5f, hh = c0.w * 0.5f;
    float4 box = make_float4(c0.x - hw, c0.y - hh, c0.x + hw, c0.y + hh);
    float sv = 0.45f * (fmaxf(box.z - box.x, 0.0f) * fmaxf(box.w - box.y, 0.0f));
    int cellx = min(15, max(0, (int)(c0.x * 0.025f)));
    int celly = min(15, max(0, (int)(c0.y * 0.025f)));
    int cell = celly * 16 + cellx;

    // ---- spatial binning ----
    if (t < 256) counts[t] = 0;
    __syncthreads();
    atomicAdd(&counts[cell], 1);
    __syncthreads();
    if (t < 256) scanbuf[t] = counts[t];
    __syncthreads();
    for (int off = 1; off < 256; off <<= 1) {
        int add = 0;
        if (t < 256 && t >= off) add = scanbuf[t - off];
        __syncthreads();
        if (t < 256) scanbuf[t] += add;
        __syncthreads();
    }
    if (t == 0) cstart[0] = 0;
    if (t < 256) { cstart[t + 1] = scanbuf[t]; counts[t] = (t == 0) ? 0 : scanbuf[t - 1]; }
    __syncthreads();
    {
        int pos = atomicAdd(&counts[cell], 1);
        g_sbox[b * TOPK + pos] = box;
        g_saux[b * TOPK + pos] = make_uint2(__float_as_uint(sv), (unsigned)t);
    }
    if (t < 257) g_cellstart[b * 257 + t] = cstart[t];
}

// ---------------- K3: sparse suppression-mask, 4 threads per entry ----------------
__global__ __launch_bounds__(512) void k_pairs() {
    __shared__ float4       sbox[TOPK];     // 16KB
    __shared__ uint2        sax[TOPK];      // 8KB
    __shared__ int          cs[257];        // 1KB
    __shared__ unsigned int rows[128 * 33]; // 16.5KB

    int b = blockIdx.y, t = threadIdx.x;
    int le = t >> 2;                  // local entry 0..127
    int q  = t & 3;                   // quarter
    int s  = blockIdx.x * 128 + le;   // global spatial entry

    for (int e = t; e < TOPK; e += 512) {
        sbox[e] = g_sbox[b * TOPK + e];
        sax[e]  = g_saux[b * TOPK + e];
    }
    for (int e = t; e < 257; e += 512) cs[e] = g_cellstart[b * 257 + e];
    __syncthreads();

    unsigned int* rowp = &rows[le * 33];
    for (int ww = q; ww < 32; ww += 4) rowp[ww] = 0u;
    __syncwarp();

    float4 bs = sbox[s];
    uint2 axs = sax[s];
    float u = __uint_as_float(axs.x);
    int rs = (int)axs.y;

    int cl = max(0, (int)((bs.x - 64.5f) * 0.025f));
    int cr = min(15, (int)((bs.z + 64.5f) * 0.025f));
    int ct = max(0, (int)((bs.y - 64.5f) * 0.025f));
    int cb = min(15, (int)((bs.w + 64.5f) * 0.025f));

    for (int cy = ct; cy <= cb; ++cy) {
        int e0 = cs[cy * 16 + cl];
        int e1 = cs[cy * 16 + cr + 1];
#pragma unroll 2
        for (int e = e0 + q; e < e1; e += 4) {
            float4 be = sbox[e];
            uint2 axe = sax[e];
            float ix1 = fmaxf(bs.x, be.x), iy1 = fmaxf(bs.y, be.y);
            float ix2 = fminf(bs.z, be.z), iy2 = fminf(bs.w, be.w);
            float inter = fmaxf(ix2 - ix1, 0.0f) * fmaxf(iy2 - iy1, 0.0f);
            float sden = u + __uint_as_float(axe.x);
            float diff = fmaf(1.45f, inter, -sden);
            bool bit;
            if (fabsf(diff) <= 2e-5f * sden) {   // rare: exact IEEE path
                float ai = fmaxf(bs.z - bs.x, 0.0f) * fmaxf(bs.w - bs.y, 0.0f);
                float aj = fmaxf(be.z - be.x, 0.0f) * fmaxf(be.w - be.y, 0.0f);
                float den = (ai + aj - inter) + 1e-9f;
                bit = (__fdiv_rn(inter, den) > IOUT);
            } else {
                bit = (diff > 0.0f);
            }
            int re = (int)axe.y;
            if (bit && re > rs) atomicOr(&rowp[re >> 5], 1u << (re & 31));
        }
    }
    __syncwarp();

    if (q == 0) {
        unsigned int wm = 0u;
#pragma unroll
        for (int ww = 0; ww < 32; ++ww) wm |= (rowp[ww] != 0u) ? (1u << ww) : 0u;
        g_wnz[b * TOPK + rs] = wm;
        if (wm) {
            unsigned int* orow = &g_mask[((long)(b * TOPK + rs)) * 32];
#pragma unroll
            for (int ww = 0; ww < 32; ++ww) orow[ww] = rowp[ww];
        }
    }
}

// ---------------- K4: rank-indexed sparse greedy scan + output ----------------
// Per-event critical path: evtrank is warp-uniform, so lane wi's word is
// fetched by ALL lanes as a uniform-address LDS broadcast, issued in parallel
// with the per-lane row load — no LDS->SHFL serialization.
__global__ __launch_bounds__(1024) void k_scan_out(const float* __restrict__ x,
                                                   float* __restrict__ out) {
    extern __shared__ unsigned int srow[];          // [TOPK * RSTR]
    __shared__ unsigned int validw[32];
    __shared__ unsigned int harw[32];
    __shared__ unsigned int keepw[32];

    int b = blockIdx.x, t = threadIdx.x;
    int w = t >> 5, lane = t & 31;

    float sc = g_topscore[b * TOPK + t];
    unsigned int vb = __ballot_sync(0xffffffffu, sc > 0.0f);
    if (lane == 0) validw[w] = vb;

    bool nzf = (g_wnz[b * TOPK + t] != 0u);
    unsigned int hb = __ballot_sync(0xffffffffu, nzf);
    if (lane == 0) harw[w] = hb;

    if (nzf) {
        const uint4* src = (const uint4*)&g_mask[((long)(b * TOPK + t)) * 32];
        uint4* dst = (uint4*)&srow[t * RSTR];
#pragma unroll
        for (int i = 0; i < 8; ++i) dst[i] = src[i];
    }
    __syncthreads();

    if (t < 32) {
        unsigned int removed = 0u;
        unsigned int vwl = validw[lane];
        for (int wi = 0; wi < 32; ++wi) {
            unsigned int alive = __shfl_sync(0xffffffffu, vwl & ~removed, wi);
            unsigned int evt = alive & harw[wi];               // uniform LDS
            while (evt) {
                int j = __ffs(evt) - 1;                        // warp-uniform
                evt &= evt - 1u;
                int rbase = ((wi << 5) + j) * RSTR;
                unsigned int rw = srow[rbase + lane];          // per-lane LDS
                unsigned int au = srow[rbase + wi];            // uniform LDS broadcast
                removed |= rw;
                alive &= ~au;
                evt &= alive;
            }
            if (lane == 0) keepw[wi] = alive;
        }
    }
    __syncthreads();

    unsigned int kept = (keepw[t >> 5] >> (t & 31)) & 1u;
    float4* orow = (float4*)(out + (long)(b * TOPK + t) * 16);
    if (kept) {
        int idx = g_topidx[b * TOPK + t];
        const float4* row = (const float4*)(x + (long)(b * NN + idx) * 16);
        float4 c0 = row[0], c1 = row[1], c2 = row[2], c3 = row[3];
        float hw = c0.z * 0.5f, hh = c0.w * 0.5f;
        orow[0] = make_float4(c0.x - hw, c0.y - hh, c0.x + hw, c0.y + hh);
        orow[1] = make_float4(sc, c1.y, c1.z, c1.w);
        orow[2] = c2;
        orow[3] = make_float4(c3.x, c3.y, c3.z, 0.0f);
    } else {
        float4 z = make_float4(0.0f, 0.0f, 0.0f, 0.0f);
        orow[0] = z; orow[1] = z; orow[2] = z; orow[3] = z;
    }
}

// ---------------- launch ----------------
extern "C" void kernel_launch(void* const* d_in, const int* in_sizes, int n_in,
                              void* d_out, int out_size) {
    const float* x = (const float*)d_in[0];
    float* out = (float*)d_out;
    (void)in_sizes; (void)n_in; (void)out_size;

    const int scan_smem = TOPK * RSTR * 4;   // 147456 bytes
    cudaFuncSetAttribute(k_scan_out, cudaFuncAttributeMaxDynamicSharedMemorySize, scan_smem);

    {
        dim3 g((NN + 1023) / 1024, BB);
        k_score<<<g, 256>>>(x);
    }
    k_topk<<<BB, 1024>>>(x);
    {
        dim3 g(8, BB);
        k_pairs<<<g, 512>>>();
    }
    k_scan_out<<<BB, 1024, scan_smem>>>(x, out);
}